// round 1
// baseline (speedup 1.0000x reference)
#include <cuda_runtime.h>
#include <math.h>

// Problem constants (fixed shapes)
#define Lq 4096
#define Dm 1536
#define NH 12
#define HDim 128
#define Cc 64
#define S1c 22
#define S2c 21
#define EPSF 1e-6f
#define INV_SQRT_D 0.08838834764831845f  // 1/sqrt(128)

// Scratch (device globals; no runtime allocation allowed)
__device__ float g_Q[Lq * Dm];
__device__ float g_K[Lq * Dm];
__device__ float g_V[Lq * Dm];
__device__ float g_A[Lq * Dm];

// ---------------------------------------------------------------------------
// GEMM: C[M,N] = X[M,K] @ W[N,K]^T + bias[N]   (both row-major, K contiguous)
// 64x64 tile, BK=16, 256 threads, 4x4 microtile, smem stored K-major so inner
// loop reads are float4.
// ---------------------------------------------------------------------------
__global__ __launch_bounds__(256) void gemm_nt_bias(
    const float* __restrict__ X, const float* __restrict__ W,
    const float* __restrict__ bias, float* __restrict__ Cout,
    int M, int Nn, int Kk)
{
    __shared__ float Xs[16][68];
    __shared__ float Ws[16][68];

    const int t  = threadIdx.x;
    const int tr = t >> 4;        // 0..15 (row group)
    const int tc = t & 15;        // 0..15 (col group)
    const int m0 = blockIdx.y * 64;
    const int n0 = blockIdx.x * 64;

    const int lr  = t >> 2;       // 0..63 load row
    const int lc4 = (t & 3) * 4;  // 0,4,8,12 load col (within BK)

    const float* Xp = X + (size_t)(m0 + lr) * Kk + lc4;
    const float* Wp = W + (size_t)(n0 + lr) * Kk + lc4;

    float acc[4][4] = {};

    for (int k0 = 0; k0 < Kk; k0 += 16) {
        float4 xa = *(const float4*)(Xp + k0);
        float4 wa = *(const float4*)(Wp + k0);
        Xs[lc4 + 0][lr] = xa.x; Xs[lc4 + 1][lr] = xa.y;
        Xs[lc4 + 2][lr] = xa.z; Xs[lc4 + 3][lr] = xa.w;
        Ws[lc4 + 0][lr] = wa.x; Ws[lc4 + 1][lr] = wa.y;
        Ws[lc4 + 2][lr] = wa.z; Ws[lc4 + 3][lr] = wa.w;
        __syncthreads();

        #pragma unroll
        for (int kk = 0; kk < 16; kk++) {
            float4 a = *(const float4*)&Xs[kk][tr * 4];
            float4 b = *(const float4*)&Ws[kk][tc * 4];
            acc[0][0] += a.x * b.x; acc[0][1] += a.x * b.y;
            acc[0][2] += a.x * b.z; acc[0][3] += a.x * b.w;
            acc[1][0] += a.y * b.x; acc[1][1] += a.y * b.y;
            acc[1][2] += a.y * b.z; acc[1][3] += a.y * b.w;
            acc[2][0] += a.z * b.x; acc[2][1] += a.z * b.y;
            acc[2][2] += a.z * b.z; acc[2][3] += a.z * b.w;
            acc[3][0] += a.w * b.x; acc[3][1] += a.w * b.y;
            acc[3][2] += a.w * b.z; acc[3][3] += a.w * b.w;
        }
        __syncthreads();
    }

    const float4 bv = *(const float4*)(bias + n0 + tc * 4);
    #pragma unroll
    for (int i = 0; i < 4; i++) {
        float4 r;
        r.x = acc[i][0] + bv.x; r.y = acc[i][1] + bv.y;
        r.z = acc[i][2] + bv.z; r.w = acc[i][3] + bv.w;
        *(float4*)(Cout + (size_t)(m0 + tr * 4 + i) * Nn + n0 + tc * 4) = r;
    }
}

// ---------------------------------------------------------------------------
// RMSNorm over full D (mean of squares + eps, rsqrt, *g) then 3D RoPE.
// One block per token row.
// ---------------------------------------------------------------------------
__global__ __launch_bounds__(256) void rmsnorm_rope(
    float* __restrict__ T, const float* __restrict__ g,
    const float* __restrict__ fcos, const float* __restrict__ fsin,
    const int* __restrict__ pF, const int* __restrict__ pH,
    const int* __restrict__ pW)
{
    const int row = blockIdx.x;
    float* p = T + (size_t)row * Dm;

    float ss = 0.f;
    for (int i = threadIdx.x; i < Dm; i += 256) {
        float v = p[i];
        ss += v * v;
    }
    // block reduce
    __shared__ float red[8];
    const int lane = threadIdx.x & 31;
    const int wid  = threadIdx.x >> 5;
    #pragma unroll
    for (int off = 16; off >= 1; off >>= 1)
        ss += __shfl_xor_sync(0xffffffffu, ss, off);
    if (lane == 0) red[wid] = ss;
    __syncthreads();
    if (wid == 0) {
        float v = (lane < 8) ? red[lane] : 0.f;
        #pragma unroll
        for (int off = 4; off >= 1; off >>= 1)
            v += __shfl_xor_sync(0xffffffffu, v, off);
        if (lane == 0) red[0] = rsqrtf(v * (1.f / Dm) + EPSF);
    }
    __syncthreads();
    const float rms = red[0];

    const int F = *pF, H = *pH, W = *pW;
    const int f  = row / (H * W);
    const int hh = (row / W) % H;
    const int ww = row % W;

    // 12 heads * 64 complex pairs = 768 pairs, each covers 2 consecutive elems
    for (int pj = threadIdx.x; pj < NH * Cc; pj += 256) {
        const int n = pj / Cc;
        const int j = pj % Cc;
        const int coord = (j < S1c) ? f : ((j < S1c + S2c) ? hh : ww);
        const float ccos = fcos[coord * Cc + j];
        const float csin = fsin[coord * Cc + j];
        const int idx = n * HDim + 2 * j;
        const float xr = p[idx]     * rms * g[idx];
        const float xi = p[idx + 1] * rms * g[idx + 1];
        p[idx]     = xr * ccos - xi * csin;
        p[idx + 1] = xr * csin + xi * ccos;
    }
}

// ---------------------------------------------------------------------------
// Flash attention, fp32. BQ=64 queries/CTA, iterate over 64-wide K tiles.
// 256 threads: (tr,tc) 16x16; each thread: 4x4 score microtile, 4x8 output.
// Dynamic smem: Qs[64][129] Ks[64][129] Vs[64][132] Ps[64][68].
// ---------------------------------------------------------------------------
#define QK_STRIDE 129
#define V_STRIDE  132
#define P_STRIDE  68
#define FLASH_SMEM ((64 * QK_STRIDE * 2 + 64 * V_STRIDE + 64 * P_STRIDE) * 4)

__global__ __launch_bounds__(256, 1) void flash_attn(
    const float* __restrict__ Q, const float* __restrict__ K,
    const float* __restrict__ V, float* __restrict__ O)
{
    extern __shared__ float sm[];
    float* Qs = sm;                           // 64*129
    float* Ks = Qs + 64 * QK_STRIDE;          // 64*129
    float* Vs = Ks + 64 * QK_STRIDE;          // 64*132
    float* Ps = Vs + 64 * V_STRIDE;           // 64*68

    const int t  = threadIdx.x;
    const int tr = t >> 4;
    const int tc = t & 15;
    const int n  = blockIdx.y;
    const int q0 = blockIdx.x * 64;

    // load Q tile (pre-scaled by 1/sqrt(d))
    for (int i = t; i < 64 * 32; i += 256) {
        const int r  = i >> 5;
        const int c4 = (i & 31) << 2;
        float4 v = *(const float4*)(Q + (size_t)(q0 + r) * Dm + n * HDim + c4);
        float* dst = Qs + r * QK_STRIDE + c4;
        dst[0] = v.x * INV_SQRT_D; dst[1] = v.y * INV_SQRT_D;
        dst[2] = v.z * INV_SQRT_D; dst[3] = v.w * INV_SQRT_D;
    }

    float m_i[4], l_i[4], o[4][8];
    #pragma unroll
    for (int i = 0; i < 4; i++) {
        m_i[i] = -1e30f; l_i[i] = 0.f;
        #pragma unroll
        for (int j = 0; j < 8; j++) o[i][j] = 0.f;
    }

    const float* aptr[4];
    const float* bptr[4];
    #pragma unroll
    for (int i = 0; i < 4; i++) aptr[i] = Qs + (4 * tr + i) * QK_STRIDE;
    #pragma unroll
    for (int j = 0; j < 4; j++) bptr[j] = Ks + (4 * tc + j) * QK_STRIDE;

    for (int kt = 0; kt < Lq / 64; kt++) {
        __syncthreads();  // previous iteration's readers done
        const int k0 = kt * 64;
        for (int i = t; i < 64 * 32; i += 256) {
            const int r  = i >> 5;
            const int c4 = (i & 31) << 2;
            float4 kv = *(const float4*)(K + (size_t)(k0 + r) * Dm + n * HDim + c4);
            float* kd = Ks + r * QK_STRIDE + c4;
            kd[0] = kv.x; kd[1] = kv.y; kd[2] = kv.z; kd[3] = kv.w;
            float4 vv = *(const float4*)(V + (size_t)(k0 + r) * Dm + n * HDim + c4);
            *(float4*)(Vs + r * V_STRIDE + c4) = vv;
        }
        __syncthreads();

        float s[4][4] = {};
        #pragma unroll 8
        for (int kk = 0; kk < HDim; kk++) {
            float a0 = aptr[0][kk], a1 = aptr[1][kk], a2 = aptr[2][kk], a3 = aptr[3][kk];
            float b0 = bptr[0][kk], b1 = bptr[1][kk], b2 = bptr[2][kk], b3 = bptr[3][kk];
            s[0][0] += a0 * b0; s[0][1] += a0 * b1; s[0][2] += a0 * b2; s[0][3] += a0 * b3;
            s[1][0] += a1 * b0; s[1][1] += a1 * b1; s[1][2] += a1 * b2; s[1][3] += a1 * b3;
            s[2][0] += a2 * b0; s[2][1] += a2 * b1; s[2][2] += a2 * b2; s[2][3] += a2 * b3;
            s[3][0] += a3 * b0; s[3][1] += a3 * b1; s[3][2] += a3 * b2; s[3][3] += a3 * b3;
        }

        // online softmax per query row (rows shared by the 16 tc-lanes)
        #pragma unroll
        for (int i = 0; i < 4; i++) {
            float rmax = fmaxf(fmaxf(s[i][0], s[i][1]), fmaxf(s[i][2], s[i][3]));
            #pragma unroll
            for (int off = 8; off >= 1; off >>= 1)
                rmax = fmaxf(rmax, __shfl_xor_sync(0xffffffffu, rmax, off));
            const float mn   = fmaxf(m_i[i], rmax);
            const float corr = __expf(m_i[i] - mn);
            m_i[i] = mn;
            float rsum = 0.f;
            #pragma unroll
            for (int j = 0; j < 4; j++) {
                s[i][j] = __expf(s[i][j] - mn);
                rsum += s[i][j];
            }
            #pragma unroll
            for (int off = 8; off >= 1; off >>= 1)
                rsum += __shfl_xor_sync(0xffffffffu, rsum, off);
            l_i[i] = l_i[i] * corr + rsum;
            #pragma unroll
            for (int j = 0; j < 8; j++) o[i][j] *= corr;
            *(float4*)&Ps[(4 * tr + i) * P_STRIDE + 4 * tc] =
                make_float4(s[i][0], s[i][1], s[i][2], s[i][3]);
        }
        __syncthreads();

        // O += P @ V
        #pragma unroll 4
        for (int kk = 0; kk < 64; kk++) {
            float p0 = Ps[(4 * tr + 0) * P_STRIDE + kk];
            float p1 = Ps[(4 * tr + 1) * P_STRIDE + kk];
            float p2 = Ps[(4 * tr + 2) * P_STRIDE + kk];
            float p3 = Ps[(4 * tr + 3) * P_STRIDE + kk];
            float4 va = *(const float4*)&Vs[kk * V_STRIDE + 8 * tc];
            float4 vb = *(const float4*)&Vs[kk * V_STRIDE + 8 * tc + 4];
            o[0][0] += p0 * va.x; o[0][1] += p0 * va.y; o[0][2] += p0 * va.z; o[0][3] += p0 * va.w;
            o[0][4] += p0 * vb.x; o[0][5] += p0 * vb.y; o[0][6] += p0 * vb.z; o[0][7] += p0 * vb.w;
            o[1][0] += p1 * va.x; o[1][1] += p1 * va.y; o[1][2] += p1 * va.z; o[1][3] += p1 * va.w;
            o[1][4] += p1 * vb.x; o[1][5] += p1 * vb.y; o[1][6] += p1 * vb.z; o[1][7] += p1 * vb.w;
            o[2][0] += p2 * va.x; o[2][1] += p2 * va.y; o[2][2] += p2 * va.z; o[2][3] += p2 * va.w;
            o[2][4] += p2 * vb.x; o[2][5] += p2 * vb.y; o[2][6] += p2 * vb.z; o[2][7] += p2 * vb.w;
            o[3][0] += p3 * va.x; o[3][1] += p3 * va.y; o[3][2] += p3 * va.z; o[3][3] += p3 * va.w;
            o[3][4] += p3 * vb.x; o[3][5] += p3 * vb.y; o[3][6] += p3 * vb.z; o[3][7] += p3 * vb.w;
        }
    }

    #pragma unroll
    for (int i = 0; i < 4; i++) {
        const float inv = 1.f / l_i[i];
        float4 ra, rb;
        ra.x = o[i][0] * inv; ra.y = o[i][1] * inv;
        ra.z = o[i][2] * inv; ra.w = o[i][3] * inv;
        rb.x = o[i][4] * inv; rb.y = o[i][5] * inv;
        rb.z = o[i][6] * inv; rb.w = o[i][7] * inv;
        float* dst = O + (size_t)(q0 + 4 * tr + i) * Dm + n * HDim + 8 * tc;
        *(float4*)dst       = ra;
        *(float4*)(dst + 4) = rb;
    }
}

// ---------------------------------------------------------------------------
// Launch
// ---------------------------------------------------------------------------
extern "C" void kernel_launch(void* const* d_in, const int* in_sizes, int n_in,
                              void* d_out, int out_size)
{
    const float* x    = (const float*)d_in[0];
    const float* wq   = (const float*)d_in[1];
    const float* wk   = (const float*)d_in[2];
    const float* wv   = (const float*)d_in[3];
    const float* wo   = (const float*)d_in[4];
    const float* bq   = (const float*)d_in[5];
    const float* bk   = (const float*)d_in[6];
    const float* bv   = (const float*)d_in[7];
    const float* bo   = (const float*)d_in[8];
    const float* gq   = (const float*)d_in[9];
    const float* gk   = (const float*)d_in[10];
    const float* fcos = (const float*)d_in[11];
    const float* fsin = (const float*)d_in[12];
    // d_in[13] = seq_lens (all == L, full attention)
    const int* pF = (const int*)d_in[14];
    const int* pH = (const int*)d_in[15];
    const int* pW = (const int*)d_in[16];
    float* out = (float*)d_out;

    float *Qp, *Kp, *Vp, *Ap;
    cudaGetSymbolAddress((void**)&Qp, g_Q);
    cudaGetSymbolAddress((void**)&Kp, g_K);
    cudaGetSymbolAddress((void**)&Vp, g_V);
    cudaGetSymbolAddress((void**)&Ap, g_A);

    dim3 gg(Dm / 64, Lq / 64);

    gemm_nt_bias<<<gg, 256>>>(x, wq, bq, Qp, Lq, Dm, Dm);
    gemm_nt_bias<<<gg, 256>>>(x, wk, bk, Kp, Lq, Dm, Dm);
    gemm_nt_bias<<<gg, 256>>>(x, wv, bv, Vp, Lq, Dm, Dm);

    rmsnorm_rope<<<Lq, 256>>>(Qp, gq, fcos, fsin, pF, pH, pW);
    rmsnorm_rope<<<Lq, 256>>>(Kp, gk, fcos, fsin, pF, pH, pW);

    cudaFuncSetAttribute(flash_attn, cudaFuncAttributeMaxDynamicSharedMemorySize,
                         FLASH_SMEM);
    flash_attn<<<dim3(Lq / 64, NH), 256, FLASH_SMEM>>>(Qp, Kp, Vp, Ap);

    gemm_nt_bias<<<gg, 256>>>(Ap, wo, bo, out, Lq, Dm, Dm);
}

// round 2
// speedup vs baseline: 4.4864x; 4.4864x over previous
#include <cuda_runtime.h>
#include <math.h>
#include <stdint.h>

// Problem constants (fixed shapes)
#define Lq 4096
#define Dm 1536
#define NH 12
#define HDim 128
#define Cc 64
#define S1c 22
#define S2c 21
#define EPSF 1e-6f

// Scratch (device globals; no runtime allocation allowed)
__device__ float g_Q[Lq * Dm];
__device__ float g_K[Lq * Dm];
__device__ float g_V[Lq * Dm];
__device__ float g_A[Lq * Dm];
__device__ float g_X[Lq * Dm];
__device__ float g_Wq[Dm * Dm];
__device__ float g_Wk[Dm * Dm];
__device__ float g_Wv[Dm * Dm];
__device__ float g_Wo[Dm * Dm];

// ---------------------------------------------------------------------------
// Helpers
// ---------------------------------------------------------------------------
__device__ __forceinline__ uint32_t f2tf(float x) {
    uint32_t r;
    asm("cvt.rna.tf32.f32 %0, %1;" : "=r"(r) : "f"(x));
    return r;
}
__device__ __forceinline__ float f2tff(float x) { return __uint_as_float(f2tf(x)); }

__device__ __forceinline__ float ex2f(float x) {
    float y;
    asm("ex2.approx.ftz.f32 %0, %1;" : "=f"(y) : "f"(x));
    return y;
}

__device__ __forceinline__ void mma8(float* c, const uint32_t* a, uint32_t b0, uint32_t b1) {
    asm volatile(
        "mma.sync.aligned.m16n8k8.row.col.f32.tf32.tf32.f32 "
        "{%0,%1,%2,%3}, {%4,%5,%6,%7}, {%8,%9}, {%0,%1,%2,%3};\n"
        : "+f"(c[0]), "+f"(c[1]), "+f"(c[2]), "+f"(c[3])
        : "r"(a[0]), "r"(a[1]), "r"(a[2]), "r"(a[3]), "r"(b0), "r"(b1));
}

__device__ __forceinline__ void cp16(float* dst, const float* src) {
    uint32_t d = (uint32_t)__cvta_generic_to_shared(dst);
    asm volatile("cp.async.cg.shared.global [%0], [%1], 16;\n" :: "r"(d), "l"(src));
}
#define CP_COMMIT asm volatile("cp.async.commit_group;\n")
#define CP_WAIT(n) asm volatile("cp.async.wait_group %0;\n" :: "n"(n))

// ---------------------------------------------------------------------------
// Elementwise round-to-nearest tf32 (pre-pass for X and W tensors)
// ---------------------------------------------------------------------------
__global__ __launch_bounds__(256) void to_tf32(const float* __restrict__ in,
                                               float* __restrict__ out, int n) {
    int i = (blockIdx.x * 256 + threadIdx.x) * 4;
    if (i < n) {
        float4 v = *(const float4*)(in + i);
        v.x = f2tff(v.x); v.y = f2tff(v.y);
        v.z = f2tff(v.z); v.w = f2tff(v.w);
        *(float4*)(out + i) = v;
    }
}

// ---------------------------------------------------------------------------
// tf32 GEMM: C[M,N] = X[M,K] @ W[N,K]^T + bias.  BM=BN=128, BK=32.
// 256 threads = 8 warps (4 M x 2 N), warp tile 32x64 = 2x8 m16n8k8 mma.
// Double-buffered cp.async. Inputs must already be tf32-exact.
// ---------------------------------------------------------------------------
#define GA_STR 36
#define G_STAGE (128 * GA_STR * 2)            // A+B per stage, floats
#define G_SMEM  (2 * G_STAGE * 4)             // bytes

__global__ __launch_bounds__(256) void gemm_tf32(
    const float* __restrict__ X, const float* __restrict__ W,
    const float* __restrict__ bias, float* __restrict__ C, int roundOut)
{
    extern __shared__ float smg[];
    const int t = threadIdx.x, lane = t & 31, wid = t >> 5;
    const int g = lane >> 2, t4 = lane & 3;
    const int wm = wid >> 1, wn = wid & 1;
    const int m0 = blockIdx.y * 128, n0 = blockIdx.x * 128;

    float acc[2][8][4];
    #pragma unroll
    for (int i = 0; i < 2; i++)
        #pragma unroll
        for (int j = 0; j < 8; j++)
            #pragma unroll
            for (int q = 0; q < 4; q++) acc[i][j][q] = 0.f;

    auto issue = [&](int kt, int b) {
        float* As = smg + b * G_STAGE;
        float* Bs = As + 128 * GA_STR;
        const int k0 = kt * 32;
        #pragma unroll
        for (int i = 0; i < 4; i++) {
            int idx = t + i * 256;
            int r = idx >> 3, c4 = (idx & 7) << 2;
            cp16(As + r * GA_STR + c4, X + (size_t)(m0 + r) * Dm + k0 + c4);
            cp16(Bs + r * GA_STR + c4, W + (size_t)(n0 + r) * Dm + k0 + c4);
        }
    };

    issue(0, 0); CP_COMMIT;
    const int KT = Dm / 32;
    for (int kt = 0; kt < KT; kt++) {
        int b = kt & 1;
        if (kt + 1 < KT) { issue(kt + 1, b ^ 1); CP_COMMIT; CP_WAIT(1); }
        else             { CP_WAIT(0); }
        __syncthreads();
        float* As = smg + b * G_STAGE;
        float* Bs = As + 128 * GA_STR;
        #pragma unroll
        for (int ks = 0; ks < 4; ks++) {
            uint32_t af[2][4], bf[8][2];
            #pragma unroll
            for (int i = 0; i < 2; i++) {
                const float* ap = As + (wm * 32 + i * 16 + g) * GA_STR + ks * 8 + t4;
                af[i][0] = __float_as_uint(ap[0]);
                af[i][1] = __float_as_uint(ap[8 * GA_STR]);
                af[i][2] = __float_as_uint(ap[4]);
                af[i][3] = __float_as_uint(ap[8 * GA_STR + 4]);
            }
            #pragma unroll
            for (int j = 0; j < 8; j++) {
                const float* bp = Bs + (wn * 64 + j * 8 + g) * GA_STR + ks * 8 + t4;
                bf[j][0] = __float_as_uint(bp[0]);
                bf[j][1] = __float_as_uint(bp[4]);
            }
            #pragma unroll
            for (int i = 0; i < 2; i++)
                #pragma unroll
                for (int j = 0; j < 8; j++)
                    mma8(acc[i][j], af[i], bf[j][0], bf[j][1]);
        }
        __syncthreads();
    }

    #pragma unroll
    for (int j = 0; j < 8; j++) {
        int col = n0 + wn * 64 + j * 8 + 2 * t4;
        float b0 = bias[col], b1 = bias[col + 1];
        #pragma unroll
        for (int i = 0; i < 2; i++) {
            int row = m0 + wm * 32 + i * 16 + g;
            float c0 = acc[i][j][0] + b0, c1 = acc[i][j][1] + b1;
            float c2 = acc[i][j][2] + b0, c3 = acc[i][j][3] + b1;
            if (roundOut) { c0 = f2tff(c0); c1 = f2tff(c1); c2 = f2tff(c2); c3 = f2tff(c3); }
            *(float2*)(C + (size_t)row * Dm + col)       = make_float2(c0, c1);
            *(float2*)(C + (size_t)(row + 8) * Dm + col) = make_float2(c2, c3);
        }
    }
}

// ---------------------------------------------------------------------------
// RMSNorm over full D then 3D RoPE; rounds outputs to tf32 (rna).
// ---------------------------------------------------------------------------
__global__ __launch_bounds__(256) void rmsnorm_rope(
    float* __restrict__ T, const float* __restrict__ g,
    const float* __restrict__ fcos, const float* __restrict__ fsin,
    const int* __restrict__ pF, const int* __restrict__ pH,
    const int* __restrict__ pW)
{
    const int row = blockIdx.x;
    float* p = T + (size_t)row * Dm;

    float ss = 0.f;
    for (int i = threadIdx.x; i < Dm; i += 256) {
        float v = p[i];
        ss += v * v;
    }
    __shared__ float red[8];
    const int lane = threadIdx.x & 31;
    const int wid = threadIdx.x >> 5;
    #pragma unroll
    for (int off = 16; off >= 1; off >>= 1)
        ss += __shfl_xor_sync(0xffffffffu, ss, off);
    if (lane == 0) red[wid] = ss;
    __syncthreads();
    if (wid == 0) {
        float v = (lane < 8) ? red[lane] : 0.f;
        #pragma unroll
        for (int off = 4; off >= 1; off >>= 1)
            v += __shfl_xor_sync(0xffffffffu, v, off);
        if (lane == 0) red[0] = rsqrtf(v * (1.f / Dm) + EPSF);
    }
    __syncthreads();
    const float rms = red[0];

    const int H = *pH, W = *pW;
    (void)pF;
    const int f = row / (H * W);
    const int hh = (row / W) % H;
    const int ww = row % W;

    for (int pj = threadIdx.x; pj < NH * Cc; pj += 256) {
        const int n = pj / Cc;
        const int j = pj % Cc;
        const int coord = (j < S1c) ? f : ((j < S1c + S2c) ? hh : ww);
        const float ccos = fcos[coord * Cc + j];
        const float csin = fsin[coord * Cc + j];
        const int idx = n * HDim + 2 * j;
        const float xr = p[idx] * rms * g[idx];
        const float xi = p[idx + 1] * rms * g[idx + 1];
        p[idx]     = f2tff(xr * ccos - xi * csin);
        p[idx + 1] = f2tff(xr * csin + xi * ccos);
    }
}

// ---------------------------------------------------------------------------
// Flash attention on tf32 mma. BQ=128, key tile 64, head dim 128.
// 256 threads = 8 warps; warp owns 16 query rows.
// Q fragments live in registers (staged once via smem).
// K/V tiles double-buffered via cp.async.
// Inputs Q,K,V must be tf32-exact (rounded by producers); P rounded at store;
// output rounded for the final tf32 GEMM.
// ---------------------------------------------------------------------------
#define KS_STR 132
#define VS_STR 136
#define PS_STR 68
#define FL_SMEM ((2 * 64 * KS_STR + 2 * 64 * VS_STR + 128 * PS_STR) * 4)

__global__ __launch_bounds__(256, 1) void flash_tf32(
    const float* __restrict__ Q, const float* __restrict__ K,
    const float* __restrict__ V, float* __restrict__ O)
{
    extern __shared__ float smf[];
    float* Ks = smf;
    float* Vs = Ks + 2 * 64 * KS_STR;
    float* Ps = Vs + 2 * 64 * VS_STR;

    const int t = threadIdx.x, lane = t & 31, wid = t >> 5;
    const int g = lane >> 2, t4 = lane & 3;
    const int head = blockIdx.y;
    const int q0 = blockIdx.x * 128;
    const float* Qg = Q + (size_t)q0 * Dm + head * HDim;
    const float* Kg0 = K + head * HDim;
    const float* Vg0 = V + head * HDim;

    // Stage Q tile (coalesced) into the Ks region, then pull fragments to regs.
    for (int i = t; i < 128 * 32; i += 256) {
        int r = i >> 5, c4 = (i & 31) << 2;
        *(float4*)(Ks + r * KS_STR + c4) = *(const float4*)(Qg + (size_t)r * Dm + c4);
    }
    __syncthreads();
    uint32_t qf[16][4];
    {
        const float* bp = Ks + (wid * 16 + g) * KS_STR;
        #pragma unroll
        for (int ks = 0; ks < 16; ks++) {
            qf[ks][0] = __float_as_uint(bp[ks * 8 + t4]);
            qf[ks][1] = __float_as_uint(bp[8 * KS_STR + ks * 8 + t4]);
            qf[ks][2] = __float_as_uint(bp[ks * 8 + t4 + 4]);
            qf[ks][3] = __float_as_uint(bp[8 * KS_STR + ks * 8 + t4 + 4]);
        }
    }
    __syncthreads();

    float o[16][4];
    #pragma unroll
    for (int j = 0; j < 16; j++) { o[j][0] = o[j][1] = o[j][2] = o[j][3] = 0.f; }
    float m0 = -1e30f, m1 = -1e30f, l0 = 0.f, l1 = 0.f;
    const float KS2 = 0.08838834764831845f * 1.4426950408889634f;  // 1/sqrt(d)*log2e

    auto issue = [&](int kt, int b) {
        const float* Kg = Kg0 + (size_t)(kt * 64) * Dm;
        const float* Vg = Vg0 + (size_t)(kt * 64) * Dm;
        float* Kd = Ks + b * 64 * KS_STR;
        float* Vd = Vs + b * 64 * VS_STR;
        #pragma unroll
        for (int i = 0; i < 8; i++) {
            int idx = t + i * 256;
            int r = idx >> 5, c4 = (idx & 31) << 2;
            cp16(Kd + r * KS_STR + c4, Kg + (size_t)r * Dm + c4);
            cp16(Vd + r * VS_STR + c4, Vg + (size_t)r * Dm + c4);
        }
    };

    issue(0, 0); CP_COMMIT;
    const int NT = Lq / 64;
    for (int kt = 0; kt < NT; kt++) {
        int b = kt & 1;
        if (kt + 1 < NT) { issue(kt + 1, b ^ 1); CP_COMMIT; CP_WAIT(1); }
        else             { CP_WAIT(0); }
        __syncthreads();

        // S = Q @ K^T (scores for 16 rows x 64 keys per warp)
        float s[8][4];
        #pragma unroll
        for (int j = 0; j < 8; j++) { s[j][0] = s[j][1] = s[j][2] = s[j][3] = 0.f; }
        const float* Kb = Ks + b * 64 * KS_STR;
        #pragma unroll
        for (int ks = 0; ks < 16; ks++) {
            #pragma unroll
            for (int j = 0; j < 8; j++) {
                const float* kp = Kb + (j * 8 + g) * KS_STR + ks * 8 + t4;
                mma8(s[j], qf[ks], __float_as_uint(kp[0]), __float_as_uint(kp[4]));
            }
        }

        // Online softmax (log2 domain; scale folded into exponent)
        float mx0 = -1e30f, mx1 = -1e30f;
        #pragma unroll
        for (int j = 0; j < 8; j++) {
            mx0 = fmaxf(mx0, fmaxf(s[j][0], s[j][1]));
            mx1 = fmaxf(mx1, fmaxf(s[j][2], s[j][3]));
        }
        mx0 *= KS2; mx1 *= KS2;
        mx0 = fmaxf(mx0, __shfl_xor_sync(0xffffffffu, mx0, 1));
        mx0 = fmaxf(mx0, __shfl_xor_sync(0xffffffffu, mx0, 2));
        mx1 = fmaxf(mx1, __shfl_xor_sync(0xffffffffu, mx1, 1));
        mx1 = fmaxf(mx1, __shfl_xor_sync(0xffffffffu, mx1, 2));
        float nm0 = fmaxf(m0, mx0), nm1 = fmaxf(m1, mx1);
        float corr0 = ex2f(m0 - nm0), corr1 = ex2f(m1 - nm1);
        m0 = nm0; m1 = nm1;
        float r0 = 0.f, r1 = 0.f;
        float* P0 = Ps + (wid * 16 + g) * PS_STR + 2 * t4;
        float* P1 = P0 + 8 * PS_STR;
        #pragma unroll
        for (int j = 0; j < 8; j++) {
            float p00 = ex2f(s[j][0] * KS2 - m0);
            float p01 = ex2f(s[j][1] * KS2 - m0);
            float p10 = ex2f(s[j][2] * KS2 - m1);
            float p11 = ex2f(s[j][3] * KS2 - m1);
            r0 += p00 + p01; r1 += p10 + p11;
            *(float2*)(P0 + j * 8) = make_float2(f2tff(p00), f2tff(p01));
            *(float2*)(P1 + j * 8) = make_float2(f2tff(p10), f2tff(p11));
        }
        r0 += __shfl_xor_sync(0xffffffffu, r0, 1);
        r0 += __shfl_xor_sync(0xffffffffu, r0, 2);
        r1 += __shfl_xor_sync(0xffffffffu, r1, 1);
        r1 += __shfl_xor_sync(0xffffffffu, r1, 2);
        l0 = l0 * corr0 + r0;
        l1 = l1 * corr1 + r1;
        #pragma unroll
        for (int j = 0; j < 16; j++) {
            o[j][0] *= corr0; o[j][1] *= corr0;
            o[j][2] *= corr1; o[j][3] *= corr1;
        }
        __syncthreads();

        // O += P @ V
        const float* Vb = Vs + b * 64 * VS_STR;
        #pragma unroll
        for (int ks = 0; ks < 8; ks++) {
            uint32_t a[4];
            const float* pp = Ps + (wid * 16 + g) * PS_STR + ks * 8 + t4;
            a[0] = __float_as_uint(pp[0]);
            a[1] = __float_as_uint(pp[8 * PS_STR]);
            a[2] = __float_as_uint(pp[4]);
            a[3] = __float_as_uint(pp[8 * PS_STR + 4]);
            #pragma unroll
            for (int j = 0; j < 16; j++) {
                const float* vp = Vb + (ks * 8 + t4) * VS_STR + j * 8 + g;
                mma8(o[j], a, __float_as_uint(vp[0]), __float_as_uint(vp[4 * VS_STR]));
            }
        }
        __syncthreads();
    }

    const float inv0 = 1.f / l0, inv1 = 1.f / l1;
    float* O0 = O + (size_t)(q0 + wid * 16 + g) * Dm + head * HDim + 2 * t4;
    float* O1 = O0 + 8 * (size_t)Dm;
    #pragma unroll
    for (int j = 0; j < 16; j++) {
        *(float2*)(O0 + j * 8) = make_float2(f2tff(o[j][0] * inv0), f2tff(o[j][1] * inv0));
        *(float2*)(O1 + j * 8) = make_float2(f2tff(o[j][2] * inv1), f2tff(o[j][3] * inv1));
    }
}

// ---------------------------------------------------------------------------
// Launch
// ---------------------------------------------------------------------------
extern "C" void kernel_launch(void* const* d_in, const int* in_sizes, int n_in,
                              void* d_out, int out_size)
{
    const float* x    = (const float*)d_in[0];
    const float* wq   = (const float*)d_in[1];
    const float* wk   = (const float*)d_in[2];
    const float* wv   = (const float*)d_in[3];
    const float* wo   = (const float*)d_in[4];
    const float* bq   = (const float*)d_in[5];
    const float* bk   = (const float*)d_in[6];
    const float* bv   = (const float*)d_in[7];
    const float* bo   = (const float*)d_in[8];
    const float* gq   = (const float*)d_in[9];
    const float* gk   = (const float*)d_in[10];
    const float* fcos = (const float*)d_in[11];
    const float* fsin = (const float*)d_in[12];
    // d_in[13] = seq_lens (all == L)
    const int* pF = (const int*)d_in[14];
    const int* pH = (const int*)d_in[15];
    const int* pW = (const int*)d_in[16];
    float* out = (float*)d_out;

    float *Qp, *Kp, *Vp, *Ap, *Xr, *Wqr, *Wkr, *Wvr, *Wor;
    cudaGetSymbolAddress((void**)&Qp, g_Q);
    cudaGetSymbolAddress((void**)&Kp, g_K);
    cudaGetSymbolAddress((void**)&Vp, g_V);
    cudaGetSymbolAddress((void**)&Ap, g_A);
    cudaGetSymbolAddress((void**)&Xr, g_X);
    cudaGetSymbolAddress((void**)&Wqr, g_Wq);
    cudaGetSymbolAddress((void**)&Wkr, g_Wk);
    cudaGetSymbolAddress((void**)&Wvr, g_Wv);
    cudaGetSymbolAddress((void**)&Wor, g_Wo);

    cudaFuncSetAttribute(gemm_tf32, cudaFuncAttributeMaxDynamicSharedMemorySize, G_SMEM);
    cudaFuncSetAttribute(flash_tf32, cudaFuncAttributeMaxDynamicSharedMemorySize, FL_SMEM);

    const int nX = Lq * Dm, nW = Dm * Dm;
    to_tf32<<<nX / 4 / 256, 256>>>(x, Xr, nX);
    to_tf32<<<nW / 4 / 256, 256>>>(wq, Wqr, nW);
    to_tf32<<<nW / 4 / 256, 256>>>(wk, Wkr, nW);
    to_tf32<<<nW / 4 / 256, 256>>>(wv, Wvr, nW);
    to_tf32<<<nW / 4 / 256, 256>>>(wo, Wor, nW);

    dim3 gg(Dm / 128, Lq / 128);
    gemm_tf32<<<gg, 256, G_SMEM>>>(Xr, Wqr, bq, Qp, 0);
    gemm_tf32<<<gg, 256, G_SMEM>>>(Xr, Wkr, bk, Kp, 0);
    gemm_tf32<<<gg, 256, G_SMEM>>>(Xr, Wvr, bv, Vp, 1);

    rmsnorm_rope<<<Lq, 256>>>(Qp, gq, fcos, fsin, pF, pH, pW);
    rmsnorm_rope<<<Lq, 256>>>(Kp, gk, fcos, fsin, pF, pH, pW);

    flash_tf32<<<dim3(Lq / 128, NH), 256, FL_SMEM>>>(Qp, Kp, Vp, Ap);

    gemm_tf32<<<gg, 256, G_SMEM>>>(Ap, Wor, bo, out, 0);
}

// round 5
// speedup vs baseline: 7.7121x; 1.7190x over previous
#include <cuda_runtime.h>
#include <cuda_fp16.h>
#include <math.h>
#include <stdint.h>

// Problem constants (fixed shapes)
#define Lq 4096
#define Dm 1536
#define NH 12
#define HDim 128
#define Cc 64
#define S1c 22
#define S2c 21
#define EPSF 1e-6f

// Scratch (device globals; no runtime allocation allowed)
__device__ __half g_Xh[Lq * Dm];
__device__ __half g_Wqh[Dm * Dm];
__device__ __half g_Wkh[Dm * Dm];
__device__ __half g_Wvh[Dm * Dm];
__device__ __half g_Woh[Dm * Dm];
__device__ __half g_Qh[Lq * Dm];
__device__ __half g_Kh[Lq * Dm];
__device__ __half g_Vh[Lq * Dm];
__device__ __half g_Vt[Dm * Lq];     // [d_global][token]
__device__ __half g_Ah[Lq * Dm];

// ---------------------------------------------------------------------------
// Helpers
// ---------------------------------------------------------------------------
__device__ __forceinline__ float ex2f(float x) {
    float y;
    asm("ex2.approx.ftz.f32 %0, %1;" : "=f"(y) : "f"(x));
    return y;
}

// fp16 mma: D[16x8] += A[16x16] * B[16x8], fp32 accum
__device__ __forceinline__ void mma16(float* c, const uint32_t* a, uint32_t b0, uint32_t b1) {
    asm volatile(
        "mma.sync.aligned.m16n8k16.row.col.f32.f16.f16.f32 "
        "{%0,%1,%2,%3}, {%4,%5,%6,%7}, {%8,%9}, {%0,%1,%2,%3};\n"
        : "+f"(c[0]), "+f"(c[1]), "+f"(c[2]), "+f"(c[3])
        : "r"(a[0]), "r"(a[1]), "r"(a[2]), "r"(a[3]), "r"(b0), "r"(b1));
}

__device__ __forceinline__ void cp16(const void* dst_smem, const void* src) {
    uint32_t d = (uint32_t)__cvta_generic_to_shared(dst_smem);
    asm volatile("cp.async.cg.shared.global [%0], [%1], 16;\n" :: "r"(d), "l"(src));
}
#define CP_COMMIT asm volatile("cp.async.commit_group;\n")
#define CP_WAIT(n) asm volatile("cp.async.wait_group %0;\n" :: "n"(n))

__device__ __forceinline__ uint32_t ldh2(const __half* p) {
    return *(const uint32_t*)p;
}

// ---------------------------------------------------------------------------
// fp32 -> fp16 conversion pre-pass (8 elems/thread)
// ---------------------------------------------------------------------------
__global__ __launch_bounds__(256) void to_half(const float* __restrict__ in,
                                               __half* __restrict__ out, int n) {
    int i = (blockIdx.x * 256 + threadIdx.x) * 8;
    if (i < n) {
        float4 v0 = *(const float4*)(in + i);
        float4 v1 = *(const float4*)(in + i + 4);
        __half2 h0 = __floats2half2_rn(v0.x, v0.y);
        __half2 h1 = __floats2half2_rn(v0.z, v0.w);
        __half2 h2 = __floats2half2_rn(v1.x, v1.y);
        __half2 h3 = __floats2half2_rn(v1.z, v1.w);
        uint4 pk;
        pk.x = *(uint32_t*)&h0; pk.y = *(uint32_t*)&h1;
        pk.z = *(uint32_t*)&h2; pk.w = *(uint32_t*)&h3;
        *(uint4*)(out + i) = pk;
    }
}

// ---------------------------------------------------------------------------
// fp16 GEMM: C[M,N] = X[M,K] @ W[N,K]^T + bias.  BM=BN=128, BK=32.
// 256 threads = 8 warps (4 M x 2 N), warp tile 32x64 = 2x8 m16n8k16 per ks.
// 5-stage cp.async pipeline. Output fp32 or fp16 per flag.
// ---------------------------------------------------------------------------
#define GSTR 40                        // smem row stride in halfs (80B)
#define GTILE (128 * GSTR)             // halfs per tile
#define GSTAGE (2 * GTILE)             // A+B per stage (halfs)
#define NSTG 5
#define G_SMEM (NSTG * GSTAGE * 2)     // bytes

__global__ __launch_bounds__(256, 2) void gemm_h(
    const __half* __restrict__ X, const __half* __restrict__ W,
    const float* __restrict__ bias, void* __restrict__ Cout, int outHalf)
{
    extern __shared__ __half smg[];
    const int t = threadIdx.x, lane = t & 31, wid = t >> 5;
    const int g = lane >> 2, t4 = lane & 3;
    const int wm = wid >> 1, wn = wid & 1;
    const int m0 = blockIdx.y * 128, n0 = blockIdx.x * 128;

    float acc[2][8][4];
    #pragma unroll
    for (int i = 0; i < 2; i++)
        #pragma unroll
        for (int j = 0; j < 8; j++)
            #pragma unroll
            for (int q = 0; q < 4; q++) acc[i][j][q] = 0.f;

    auto issue = [&](int kt) {
        __half* As = smg + (kt % NSTG) * GSTAGE;
        __half* Bs = As + GTILE;
        const int k0 = kt * 32;
        #pragma unroll
        for (int i = 0; i < 2; i++) {
            int idx = t + i * 256;           // A chunks 0..511
            int r = idx >> 2, c = idx & 3;   // c: 16B chunk (8 halfs)
            cp16(As + r * GSTR + c * 8, X + (size_t)(m0 + r) * Dm + k0 + c * 8);
        }
        #pragma unroll
        for (int i = 0; i < 2; i++) {
            int idx = t + i * 256;
            int r = idx >> 2, c = idx & 3;
            cp16(Bs + r * GSTR + c * 8, W + (size_t)(n0 + r) * Dm + k0 + c * 8);
        }
        CP_COMMIT;
    };

    issue(0); issue(1); issue(2); issue(3);

    const int KT = Dm / 32;
    for (int kt = 0; kt < KT; kt++) {
        CP_WAIT(3);
        __syncthreads();
        const __half* As = smg + (kt % NSTG) * GSTAGE;
        const __half* Bs = As + GTILE;
        #pragma unroll
        for (int ks = 0; ks < 2; ks++) {
            uint32_t af[2][4], bf[8][2];
            #pragma unroll
            for (int i = 0; i < 2; i++) {
                const __half* ap = As + (wm * 32 + i * 16 + g) * GSTR + ks * 16 + 2 * t4;
                af[i][0] = ldh2(ap);
                af[i][1] = ldh2(ap + 8 * GSTR);
                af[i][2] = ldh2(ap + 8);
                af[i][3] = ldh2(ap + 8 * GSTR + 8);
            }
            #pragma unroll
            for (int j = 0; j < 8; j++) {
                const __half* bp = Bs + (wn * 64 + j * 8 + g) * GSTR + ks * 16 + 2 * t4;
                bf[j][0] = ldh2(bp);
                bf[j][1] = ldh2(bp + 8);
            }
            #pragma unroll
            for (int i = 0; i < 2; i++)
                #pragma unroll
                for (int j = 0; j < 8; j++)
                    mma16(acc[i][j], af[i], bf[j][0], bf[j][1]);
        }
        __syncthreads();
        if (kt + 4 < KT) issue(kt + 4);
    }

    #pragma unroll
    for (int j = 0; j < 8; j++) {
        int col = n0 + wn * 64 + j * 8 + 2 * t4;
        float b0 = bias[col], b1 = bias[col + 1];
        #pragma unroll
        for (int i = 0; i < 2; i++) {
            int row = m0 + wm * 32 + i * 16 + g;
            float c00 = acc[i][j][0] + b0, c01 = acc[i][j][1] + b1;
            float c10 = acc[i][j][2] + b0, c11 = acc[i][j][3] + b1;
            if (outHalf) {
                __half* C = (__half*)Cout;
                *(__half2*)(C + (size_t)row * Dm + col) = __floats2half2_rn(c00, c01);
                *(__half2*)(C + (size_t)(row + 8) * Dm + col) = __floats2half2_rn(c10, c11);
            } else {
                float* C = (float*)Cout;
                *(float2*)(C + (size_t)row * Dm + col) = make_float2(c00, c01);
                *(float2*)(C + (size_t)(row + 8) * Dm + col) = make_float2(c10, c11);
            }
        }
    }
}

// ---------------------------------------------------------------------------
// RMSNorm over full D then 3D RoPE on half tensors (fp32 math inside).
// ---------------------------------------------------------------------------
__global__ __launch_bounds__(256) void rmsnorm_rope_h(
    __half* __restrict__ T, const float* __restrict__ g,
    const float* __restrict__ fcos, const float* __restrict__ fsin,
    const int* __restrict__ pH, const int* __restrict__ pW)
{
    const int row = blockIdx.x;
    __half* p = T + (size_t)row * Dm;

    float ss = 0.f;
    for (int i = threadIdx.x * 2; i < Dm; i += 512) {
        float2 v = __half22float2(*(const __half2*)(p + i));
        ss += v.x * v.x + v.y * v.y;
    }
    __shared__ float red[8];
    const int lane = threadIdx.x & 31;
    const int wid = threadIdx.x >> 5;
    #pragma unroll
    for (int off = 16; off >= 1; off >>= 1)
        ss += __shfl_xor_sync(0xffffffffu, ss, off);
    if (lane == 0) red[wid] = ss;
    __syncthreads();
    if (wid == 0) {
        float v = (lane < 8) ? red[lane] : 0.f;
        #pragma unroll
        for (int off = 4; off >= 1; off >>= 1)
            v += __shfl_xor_sync(0xffffffffu, v, off);
        if (lane == 0) red[0] = rsqrtf(v * (1.f / Dm) + EPSF);
    }
    __syncthreads();
    const float rms = red[0];

    const int H = *pH, W = *pW;
    const int f = row / (H * W);
    const int hh = (row / W) % H;
    const int ww = row % W;

    for (int pj = threadIdx.x; pj < NH * Cc; pj += 256) {
        const int n = pj / Cc;
        const int j = pj % Cc;
        const int coord = (j < S1c) ? f : ((j < S1c + S2c) ? hh : ww);
        const float ccos = fcos[coord * Cc + j];
        const float csin = fsin[coord * Cc + j];
        const int idx = n * HDim + 2 * j;
        float2 v = __half22float2(*(const __half2*)(p + idx));
        const float xr = v.x * rms * g[idx];
        const float xi = v.y * rms * g[idx + 1];
        *(__half2*)(p + idx) = __floats2half2_rn(xr * ccos - xi * csin,
                                                 xr * csin + xi * ccos);
    }
}

// ---------------------------------------------------------------------------
// Transpose V: Vh[token][dglobal] -> Vt[dglobal][token]
// ---------------------------------------------------------------------------
__global__ __launch_bounds__(256) void transpose_v(const __half* __restrict__ Vh,
                                                   __half* __restrict__ Vt)
{
    __shared__ __half tile[32][33];
    const int tx = threadIdx.x & 31, ty = threadIdx.x >> 5;  // 32 x 8
    const int t0 = blockIdx.x * 32;   // token tile
    const int d0 = blockIdx.y * 32;   // d tile
    #pragma unroll
    for (int i = 0; i < 4; i++)
        tile[ty + i * 8][tx] = Vh[(size_t)(t0 + ty + i * 8) * Dm + d0 + tx];
    __syncthreads();
    #pragma unroll
    for (int i = 0; i < 4; i++)
        Vt[(size_t)(d0 + ty + i * 8) * Lq + t0 + tx] = tile[tx][ty + i * 8];
}

// ---------------------------------------------------------------------------
// Flash attention, fp16 mma. BQ=128, key tile 64, head dim 128.
// 256 threads = 8 warps; warp owns 16 query rows. Q frags in regs.
// K double-buffered [64][136]h, Vt double-buffered [128][72]h, P [128][72]h.
// ---------------------------------------------------------------------------
#define KSTR 136
#define VSTR 72
#define PSTR 72
#define FL_SMEM ((2 * 64 * KSTR + 2 * 128 * VSTR + 128 * PSTR) * 2)

__global__ __launch_bounds__(256, 1) void flash_h(
    const __half* __restrict__ Q, const __half* __restrict__ K,
    const __half* __restrict__ Vt, __half* __restrict__ O)
{
    extern __shared__ __half smf[];
    __half* Ks = smf;                         // 2 stages x 64 x KSTR
    __half* Vs = Ks + 2 * 64 * KSTR;          // 2 stages x 128 x VSTR
    __half* Ps = Vs + 2 * 128 * VSTR;         // 128 x PSTR

    const int t = threadIdx.x, lane = t & 31, wid = t >> 5;
    const int g = lane >> 2, t4 = lane & 3;
    const int head = blockIdx.y;
    const int q0 = blockIdx.x * 128;
    const __half* Qg = Q + (size_t)q0 * Dm + head * HDim;
    const __half* Kg0 = K + head * HDim;
    const __half* Vtg = Vt + (size_t)(head * HDim) * Lq;

    // Stage Q (128 x 128 halfs) into Ks area (both stages), coalesced.
    for (int i = t; i < 128 * 16; i += 256) {
        int r = i >> 4, c = i & 15;   // c: 16B chunk
        *(uint4*)(Ks + r * KSTR + c * 8) = *(const uint4*)(Qg + (size_t)r * Dm + c * 8);
    }
    __syncthreads();
    uint32_t qf[8][4];
    {
        const __half* bp = Ks + (wid * 16 + g) * KSTR;
        #pragma unroll
        for (int ks = 0; ks < 8; ks++) {
            qf[ks][0] = ldh2(bp + ks * 16 + 2 * t4);
            qf[ks][1] = ldh2(bp + 8 * KSTR + ks * 16 + 2 * t4);
            qf[ks][2] = ldh2(bp + ks * 16 + 2 * t4 + 8);
            qf[ks][3] = ldh2(bp + 8 * KSTR + ks * 16 + 2 * t4 + 8);
        }
    }
    __syncthreads();

    float o[16][4];
    #pragma unroll
    for (int j = 0; j < 16; j++) { o[j][0] = o[j][1] = o[j][2] = o[j][3] = 0.f; }
    float m0 = -1e30f, m1 = -1e30f, l0 = 0.f, l1 = 0.f;
    const float KS2 = 0.08838834764831845f * 1.4426950408889634f;  // 1/sqrt(d)*log2e

    auto issue = [&](int kt, int b) {
        const __half* Kg = Kg0 + (size_t)(kt * 64) * Dm;
        __half* Kd = Ks + b * 64 * KSTR;
        __half* Vd = Vs + b * 128 * VSTR;
        #pragma unroll
        for (int i = 0; i < 4; i++) {
            int idx = t + i * 256;                 // 1024 K chunks (64 rows x 16)
            int r = idx >> 4, c = idx & 15;
            cp16(Kd + r * KSTR + c * 8, Kg + (size_t)r * Dm + c * 8);
        }
        #pragma unroll
        for (int i = 0; i < 4; i++) {
            int idx = t + i * 256;                 // 1024 Vt chunks (128 rows x 8)
            int r = idx >> 3, c = idx & 7;
            cp16(Vd + r * VSTR + c * 8, Vtg + (size_t)r * Lq + kt * 64 + c * 8);
        }
        CP_COMMIT;
    };

    issue(0, 0);
    const int NT = Lq / 64;
    for (int kt = 0; kt < NT; kt++) {
        int b = kt & 1;
        if (kt + 1 < NT) { issue(kt + 1, b ^ 1); CP_WAIT(1); }
        else             { CP_WAIT(0); }
        __syncthreads();

        // S = Q @ K^T : 16 rows x 64 keys per warp
        float s[8][4];
        #pragma unroll
        for (int j = 0; j < 8; j++) { s[j][0] = s[j][1] = s[j][2] = s[j][3] = 0.f; }
        const __half* Kb = Ks + b * 64 * KSTR;
        #pragma unroll
        for (int ks = 0; ks < 8; ks++) {
            #pragma unroll
            for (int j = 0; j < 8; j++) {
                const __half* kp = Kb + (j * 8 + g) * KSTR + ks * 16 + 2 * t4;
                mma16(s[j], qf[ks], ldh2(kp), ldh2(kp + 8));
            }
        }

        // Online softmax (log2 domain)
        float mx0 = -1e30f, mx1 = -1e30f;
        #pragma unroll
        for (int j = 0; j < 8; j++) {
            mx0 = fmaxf(mx0, fmaxf(s[j][0], s[j][1]));
            mx1 = fmaxf(mx1, fmaxf(s[j][2], s[j][3]));
        }
        mx0 *= KS2; mx1 *= KS2;
        mx0 = fmaxf(mx0, __shfl_xor_sync(0xffffffffu, mx0, 1));
        mx0 = fmaxf(mx0, __shfl_xor_sync(0xffffffffu, mx0, 2));
        mx1 = fmaxf(mx1, __shfl_xor_sync(0xffffffffu, mx1, 1));
        mx1 = fmaxf(mx1, __shfl_xor_sync(0xffffffffu, mx1, 2));
        float nm0 = fmaxf(m0, mx0), nm1 = fmaxf(m1, mx1);
        float corr0 = ex2f(m0 - nm0), corr1 = ex2f(m1 - nm1);
        m0 = nm0; m1 = nm1;
        float r0 = 0.f, r1 = 0.f;
        __half* P0 = Ps + (wid * 16 + g) * PSTR + 2 * t4;
        __half* P1 = P0 + 8 * PSTR;
        #pragma unroll
        for (int j = 0; j < 8; j++) {
            float p00 = ex2f(s[j][0] * KS2 - m0);
            float p01 = ex2f(s[j][1] * KS2 - m0);
            float p10 = ex2f(s[j][2] * KS2 - m1);
            float p11 = ex2f(s[j][3] * KS2 - m1);
            r0 += p00 + p01; r1 += p10 + p11;
            *(__half2*)(P0 + j * 8) = __floats2half2_rn(p00, p01);
            *(__half2*)(P1 + j * 8) = __floats2half2_rn(p10, p11);
        }
        r0 += __shfl_xor_sync(0xffffffffu, r0, 1);
        r0 += __shfl_xor_sync(0xffffffffu, r0, 2);
        r1 += __shfl_xor_sync(0xffffffffu, r1, 1);
        r1 += __shfl_xor_sync(0xffffffffu, r1, 2);
        l0 = l0 * corr0 + r0;
        l1 = l1 * corr1 + r1;
        #pragma unroll
        for (int j = 0; j < 16; j++) {
            o[j][0] *= corr0; o[j][1] *= corr0;
            o[j][2] *= corr1; o[j][3] *= corr1;
        }
        __syncthreads();

        // O += P @ V  (P: 16x64, Vt tile: [d=128][key=64])
        const __half* Vb = Vs + b * 128 * VSTR;
        #pragma unroll
        for (int ks = 0; ks < 4; ks++) {
            uint32_t a[4];
            const __half* pp = Ps + (wid * 16 + g) * PSTR + ks * 16 + 2 * t4;
            a[0] = ldh2(pp);
            a[1] = ldh2(pp + 8 * PSTR);
            a[2] = ldh2(pp + 8);
            a[3] = ldh2(pp + 8 * PSTR + 8);
            #pragma unroll
            for (int j = 0; j < 16; j++) {
                const __half* vp = Vb + (j * 8 + g) * VSTR + ks * 16 + 2 * t4;
                mma16(o[j], a, ldh2(vp), ldh2(vp + 8));
            }
        }
        __syncthreads();
    }

    const float inv0 = 1.f / l0, inv1 = 1.f / l1;
    __half* O0 = O + (size_t)(q0 + wid * 16 + g) * Dm + head * HDim + 2 * t4;
    __half* O1 = O0 + 8 * (size_t)Dm;
    #pragma unroll
    for (int j = 0; j < 16; j++) {
        *(__half2*)(O0 + j * 8) = __floats2half2_rn(o[j][0] * inv0, o[j][1] * inv0);
        *(__half2*)(O1 + j * 8) = __floats2half2_rn(o[j][2] * inv1, o[j][3] * inv1);
    }
}

// ---------------------------------------------------------------------------
// Launch
// ---------------------------------------------------------------------------
extern "C" void kernel_launch(void* const* d_in, const int* in_sizes, int n_in,
                              void* d_out, int out_size)
{
    const float* x    = (const float*)d_in[0];
    const float* wq   = (const float*)d_in[1];
    const float* wk   = (const float*)d_in[2];
    const float* wv   = (const float*)d_in[3];
    const float* wo   = (const float*)d_in[4];
    const float* bq   = (const float*)d_in[5];
    const float* bk   = (const float*)d_in[6];
    const float* bv   = (const float*)d_in[7];
    const float* bo   = (const float*)d_in[8];
    const float* gq   = (const float*)d_in[9];
    const float* gk   = (const float*)d_in[10];
    const float* fcos = (const float*)d_in[11];
    const float* fsin = (const float*)d_in[12];
    // d_in[13] = seq_lens (all == L)
    const int* pH = (const int*)d_in[15];
    const int* pW = (const int*)d_in[16];
    float* out = (float*)d_out;

    __half *Xh, *Wqh, *Wkh, *Wvh, *Woh, *Qh, *Kh, *Vh, *Vt, *Ah;
    cudaGetSymbolAddress((void**)&Xh, g_Xh);
    cudaGetSymbolAddress((void**)&Wqh, g_Wqh);
    cudaGetSymbolAddress((void**)&Wkh, g_Wkh);
    cudaGetSymbolAddress((void**)&Wvh, g_Wvh);
    cudaGetSymbolAddress((void**)&Woh, g_Woh);
    cudaGetSymbolAddress((void**)&Qh, g_Qh);
    cudaGetSymbolAddress((void**)&Kh, g_Kh);
    cudaGetSymbolAddress((void**)&Vh, g_Vh);
    cudaGetSymbolAddress((void**)&Vt, g_Vt);
    cudaGetSymbolAddress((void**)&Ah, g_Ah);

    cudaFuncSetAttribute(gemm_h, cudaFuncAttributeMaxDynamicSharedMemorySize, G_SMEM);
    cudaFuncSetAttribute(flash_h, cudaFuncAttributeMaxDynamicSharedMemorySize, FL_SMEM);

    const int nX = Lq * Dm, nW = Dm * Dm;
    to_half<<<nX / 8 / 256, 256>>>(x, Xh, nX);
    to_half<<<nW / 8 / 256, 256>>>(wq, Wqh, nW);
    to_half<<<nW / 8 / 256, 256>>>(wk, Wkh, nW);
    to_half<<<nW / 8 / 256, 256>>>(wv, Wvh, nW);
    to_half<<<nW / 8 / 256, 256>>>(wo, Woh, nW);

    dim3 gg(Dm / 128, Lq / 128);
    gemm_h<<<gg, 256, G_SMEM>>>(Xh, Wqh, bq, Qh, 1);
    gemm_h<<<gg, 256, G_SMEM>>>(Xh, Wkh, bk, Kh, 1);
    gemm_h<<<gg, 256, G_SMEM>>>(Xh, Wvh, bv, Vh, 1);

    rmsnorm_rope_h<<<Lq, 256>>>(Qh, gq, fcos, fsin, pH, pW);
    rmsnorm_rope_h<<<Lq, 256>>>(Kh, gk, fcos, fsin, pH, pW);

    transpose_v<<<dim3(Lq / 32, Dm / 32), 256>>>(Vh, Vt);

    flash_h<<<dim3(Lq / 128, NH), 256, FL_SMEM>>>(Qh, Kh, Vt, Ah);

    gemm_h<<<gg, 256, G_SMEM>>>(Ah, Woh, bo, out, 0);
}

// round 6
// speedup vs baseline: 8.2801x; 1.0737x over previous
#include <cuda_runtime.h>
#include <cuda_fp16.h>
#include <math.h>
#include <stdint.h>

// Problem constants (fixed shapes)
#define Lq 4096
#define Dm 1536
#define NH 12
#define HDim 128
#define Cc 64
#define S1c 22
#define S2c 21
#define EPSF 1e-6f

// Scratch (device globals; no runtime allocation allowed)
__device__ __half g_Xh[Lq * Dm];
__device__ __half g_Wqh[Dm * Dm];
__device__ __half g_Wkh[Dm * Dm];
__device__ __half g_Wvh[Dm * Dm];
__device__ __half g_Woh[Dm * Dm];
__device__ __half g_Qh[Lq * Dm];
__device__ __half g_Kh[Lq * Dm];
__device__ __half g_Vh[Lq * Dm];
__device__ __half g_Vt[Dm * Lq];     // [d_global][token]
__device__ __half g_Ah[Lq * Dm];

// ---------------------------------------------------------------------------
// Helpers
// ---------------------------------------------------------------------------
__device__ __forceinline__ float ex2f(float x) {
    float y;
    asm("ex2.approx.ftz.f32 %0, %1;" : "=f"(y) : "f"(x));
    return y;
}

// fp16 mma: D[16x8] += A[16x16] * B[16x8], fp32 accum
__device__ __forceinline__ void mma16(float* c, const uint32_t* a, uint32_t b0, uint32_t b1) {
    asm volatile(
        "mma.sync.aligned.m16n8k16.row.col.f32.f16.f16.f32 "
        "{%0,%1,%2,%3}, {%4,%5,%6,%7}, {%8,%9}, {%0,%1,%2,%3};\n"
        : "+f"(c[0]), "+f"(c[1]), "+f"(c[2]), "+f"(c[3])
        : "r"(a[0]), "r"(a[1]), "r"(a[2]), "r"(a[3]), "r"(b0), "r"(b1));
}

__device__ __forceinline__ void cp16(const void* dst_smem, const void* src) {
    uint32_t d = (uint32_t)__cvta_generic_to_shared(dst_smem);
    asm volatile("cp.async.cg.shared.global [%0], [%1], 16;\n" :: "r"(d), "l"(src));
}
#define CP_COMMIT asm volatile("cp.async.commit_group;\n")
#define CP_WAIT(n) asm volatile("cp.async.wait_group %0;\n" :: "n"(n))

__device__ __forceinline__ uint32_t ldh2(const __half* p) {
    return *(const uint32_t*)p;
}
__device__ __forceinline__ uint32_t packh2(float a, float b) {
    __half2 h = __floats2half2_rn(a, b);
    return *(uint32_t*)&h;
}

// ---------------------------------------------------------------------------
// fp32 -> fp16 conversion pre-pass (8 elems/thread)
// ---------------------------------------------------------------------------
__global__ __launch_bounds__(256) void to_half(const float* __restrict__ in,
                                               __half* __restrict__ out, int n) {
    int i = (blockIdx.x * 256 + threadIdx.x) * 8;
    if (i < n) {
        float4 v0 = *(const float4*)(in + i);
        float4 v1 = *(const float4*)(in + i + 4);
        __half2 h0 = __floats2half2_rn(v0.x, v0.y);
        __half2 h1 = __floats2half2_rn(v0.z, v0.w);
        __half2 h2 = __floats2half2_rn(v1.x, v1.y);
        __half2 h3 = __floats2half2_rn(v1.z, v1.w);
        uint4 pk;
        pk.x = *(uint32_t*)&h0; pk.y = *(uint32_t*)&h1;
        pk.z = *(uint32_t*)&h2; pk.w = *(uint32_t*)&h3;
        *(uint4*)(out + i) = pk;
    }
}

// 4 weight matrices in one launch (grid.y selects tensor)
__global__ __launch_bounds__(256) void to_half4(
    const float* __restrict__ w0, const float* __restrict__ w1,
    const float* __restrict__ w2, const float* __restrict__ w3,
    __half* __restrict__ o0, __half* __restrict__ o1,
    __half* __restrict__ o2, __half* __restrict__ o3, int n)
{
    const float* in; __half* out;
    switch (blockIdx.y) {
        case 0: in = w0; out = o0; break;
        case 1: in = w1; out = o1; break;
        case 2: in = w2; out = o2; break;
        default: in = w3; out = o3; break;
    }
    int i = (blockIdx.x * 256 + threadIdx.x) * 8;
    if (i < n) {
        float4 v0 = *(const float4*)(in + i);
        float4 v1 = *(const float4*)(in + i + 4);
        uint4 pk;
        pk.x = packh2(v0.x, v0.y); pk.y = packh2(v0.z, v0.w);
        pk.z = packh2(v1.x, v1.y); pk.w = packh2(v1.z, v1.w);
        *(uint4*)(out + i) = pk;
    }
}

// ---------------------------------------------------------------------------
// fp16 GEMM: C[M,N] = X[M,K] @ W[N,K]^T + bias.  BM=BN=128, BK=32.
// ---------------------------------------------------------------------------
#define GSTR 40
#define GTILE (128 * GSTR)
#define GSTAGE (2 * GTILE)
#define NSTG 5
#define G_SMEM (NSTG * GSTAGE * 2)

__global__ __launch_bounds__(256, 2) void gemm_h(
    const __half* __restrict__ X, const __half* __restrict__ W,
    const float* __restrict__ bias, void* __restrict__ Cout, int outHalf)
{
    extern __shared__ __half smg[];
    const int t = threadIdx.x, lane = t & 31, wid = t >> 5;
    const int g = lane >> 2, t4 = lane & 3;
    const int wm = wid >> 1, wn = wid & 1;
    const int m0 = blockIdx.y * 128, n0 = blockIdx.x * 128;

    float acc[2][8][4];
    #pragma unroll
    for (int i = 0; i < 2; i++)
        #pragma unroll
        for (int j = 0; j < 8; j++)
            #pragma unroll
            for (int q = 0; q < 4; q++) acc[i][j][q] = 0.f;

    auto issue = [&](int kt) {
        __half* As = smg + (kt % NSTG) * GSTAGE;
        __half* Bs = As + GTILE;
        const int k0 = kt * 32;
        #pragma unroll
        for (int i = 0; i < 2; i++) {
            int idx = t + i * 256;
            int r = idx >> 2, c = idx & 3;
            cp16(As + r * GSTR + c * 8, X + (size_t)(m0 + r) * Dm + k0 + c * 8);
        }
        #pragma unroll
        for (int i = 0; i < 2; i++) {
            int idx = t + i * 256;
            int r = idx >> 2, c = idx & 3;
            cp16(Bs + r * GSTR + c * 8, W + (size_t)(n0 + r) * Dm + k0 + c * 8);
        }
        CP_COMMIT;
    };

    issue(0); issue(1); issue(2); issue(3);

    const int KT = Dm / 32;
    for (int kt = 0; kt < KT; kt++) {
        CP_WAIT(3);
        __syncthreads();
        const __half* As = smg + (kt % NSTG) * GSTAGE;
        const __half* Bs = As + GTILE;
        #pragma unroll
        for (int ks = 0; ks < 2; ks++) {
            uint32_t af[2][4], bf[8][2];
            #pragma unroll
            for (int i = 0; i < 2; i++) {
                const __half* ap = As + (wm * 32 + i * 16 + g) * GSTR + ks * 16 + 2 * t4;
                af[i][0] = ldh2(ap);
                af[i][1] = ldh2(ap + 8 * GSTR);
                af[i][2] = ldh2(ap + 8);
                af[i][3] = ldh2(ap + 8 * GSTR + 8);
            }
            #pragma unroll
            for (int j = 0; j < 8; j++) {
                const __half* bp = Bs + (wn * 64 + j * 8 + g) * GSTR + ks * 16 + 2 * t4;
                bf[j][0] = ldh2(bp);
                bf[j][1] = ldh2(bp + 8);
            }
            #pragma unroll
            for (int i = 0; i < 2; i++)
                #pragma unroll
                for (int j = 0; j < 8; j++)
                    mma16(acc[i][j], af[i], bf[j][0], bf[j][1]);
        }
        __syncthreads();
        if (kt + 4 < KT) issue(kt + 4);
    }

    #pragma unroll
    for (int j = 0; j < 8; j++) {
        int col = n0 + wn * 64 + j * 8 + 2 * t4;
        float b0 = bias[col], b1 = bias[col + 1];
        #pragma unroll
        for (int i = 0; i < 2; i++) {
            int row = m0 + wm * 32 + i * 16 + g;
            float c00 = acc[i][j][0] + b0, c01 = acc[i][j][1] + b1;
            float c10 = acc[i][j][2] + b0, c11 = acc[i][j][3] + b1;
            if (outHalf) {
                __half* C = (__half*)Cout;
                *(__half2*)(C + (size_t)row * Dm + col) = __floats2half2_rn(c00, c01);
                *(__half2*)(C + (size_t)(row + 8) * Dm + col) = __floats2half2_rn(c10, c11);
            } else {
                float* C = (float*)Cout;
                *(float2*)(C + (size_t)row * Dm + col) = make_float2(c00, c01);
                *(float2*)(C + (size_t)(row + 8) * Dm + col) = make_float2(c10, c11);
            }
        }
    }
}

// ---------------------------------------------------------------------------
// RMSNorm + 3D RoPE on Q and K (grid.y = 0: Q, 1: K)
// ---------------------------------------------------------------------------
__global__ __launch_bounds__(256) void rmsnorm_rope_h(
    __half* __restrict__ Tq, __half* __restrict__ Tk,
    const float* __restrict__ gqv, const float* __restrict__ gkv,
    const float* __restrict__ fcos, const float* __restrict__ fsin,
    const int* __restrict__ pH, const int* __restrict__ pW)
{
    __half* T = blockIdx.y ? Tk : Tq;
    const float* g = blockIdx.y ? gkv : gqv;
    const int row = blockIdx.x;
    __half* p = T + (size_t)row * Dm;

    float ss = 0.f;
    for (int i = threadIdx.x * 2; i < Dm; i += 512) {
        float2 v = __half22float2(*(const __half2*)(p + i));
        ss += v.x * v.x + v.y * v.y;
    }
    __shared__ float red[8];
    const int lane = threadIdx.x & 31;
    const int wid = threadIdx.x >> 5;
    #pragma unroll
    for (int off = 16; off >= 1; off >>= 1)
        ss += __shfl_xor_sync(0xffffffffu, ss, off);
    if (lane == 0) red[wid] = ss;
    __syncthreads();
    if (wid == 0) {
        float v = (lane < 8) ? red[lane] : 0.f;
        #pragma unroll
        for (int off = 4; off >= 1; off >>= 1)
            v += __shfl_xor_sync(0xffffffffu, v, off);
        if (lane == 0) red[0] = rsqrtf(v * (1.f / Dm) + EPSF);
    }
    __syncthreads();
    const float rms = red[0];

    const int H = *pH, W = *pW;
    const int f = row / (H * W);
    const int hh = (row / W) % H;
    const int ww = row % W;

    for (int pj = threadIdx.x; pj < NH * Cc; pj += 256) {
        const int n = pj / Cc;
        const int j = pj % Cc;
        const int coord = (j < S1c) ? f : ((j < S1c + S2c) ? hh : ww);
        const float ccos = fcos[coord * Cc + j];
        const float csin = fsin[coord * Cc + j];
        const int idx = n * HDim + 2 * j;
        float2 v = __half22float2(*(const __half2*)(p + idx));
        const float xr = v.x * rms * g[idx];
        const float xi = v.y * rms * g[idx + 1];
        *(__half2*)(p + idx) = __floats2half2_rn(xr * ccos - xi * csin,
                                                 xr * csin + xi * ccos);
    }
}

// ---------------------------------------------------------------------------
// Transpose V: Vh[token][dglobal] -> Vt[dglobal][token]
// ---------------------------------------------------------------------------
__global__ __launch_bounds__(256) void transpose_v(const __half* __restrict__ Vh,
                                                   __half* __restrict__ Vt)
{
    __shared__ __half tile[32][33];
    const int tx = threadIdx.x & 31, ty = threadIdx.x >> 5;
    const int t0 = blockIdx.x * 32;
    const int d0 = blockIdx.y * 32;
    #pragma unroll
    for (int i = 0; i < 4; i++)
        tile[ty + i * 8][tx] = Vh[(size_t)(t0 + ty + i * 8) * Dm + d0 + tx];
    __syncthreads();
    #pragma unroll
    for (int i = 0; i < 4; i++)
        Vt[(size_t)(d0 + ty + i * 8) * Lq + t0 + tx] = tile[tx][ty + i * 8];
}

// ---------------------------------------------------------------------------
// Flash attention, fp16 mma. BQ=128, key tile 64, head dim 128.
// 256 threads = 8 warps; warp owns 16 query rows. Q frags in regs.
// P kept entirely in registers (S accum fragments repacked as A fragments).
// 4-stage cp.async ring, ONE __syncthreads per iteration.
// ---------------------------------------------------------------------------
#define KSTR 136
#define VSTR 72
#define FNST 4
#define FL_SMEM ((FNST * 64 * KSTR + FNST * 128 * VSTR) * 2)

__global__ __launch_bounds__(256, 1) void flash_h(
    const __half* __restrict__ Q, const __half* __restrict__ K,
    const __half* __restrict__ Vt, __half* __restrict__ O)
{
    extern __shared__ __half smf[];
    __half* Ks = smf;                          // FNST x 64 x KSTR
    __half* Vs = Ks + FNST * 64 * KSTR;        // FNST x 128 x VSTR

    const int t = threadIdx.x, lane = t & 31, wid = t >> 5;
    const int g = lane >> 2, t4 = lane & 3;
    const int head = blockIdx.y;
    const int q0 = blockIdx.x * 128;
    const __half* Qg = Q + (size_t)q0 * Dm + head * HDim;
    const __half* Kg0 = K + head * HDim;
    const __half* Vtg = Vt + (size_t)(head * HDim) * Lq;

    // Stage Q (128 x 128 halfs) into Ks area, then fragments -> registers.
    for (int i = t; i < 128 * 16; i += 256) {
        int r = i >> 4, c = i & 15;
        *(uint4*)(Ks + r * KSTR + c * 8) = *(const uint4*)(Qg + (size_t)r * Dm + c * 8);
    }
    __syncthreads();
    uint32_t qf[8][4];
    {
        const __half* bp = Ks + (wid * 16 + g) * KSTR;
        #pragma unroll
        for (int ks = 0; ks < 8; ks++) {
            qf[ks][0] = ldh2(bp + ks * 16 + 2 * t4);
            qf[ks][1] = ldh2(bp + 8 * KSTR + ks * 16 + 2 * t4);
            qf[ks][2] = ldh2(bp + ks * 16 + 2 * t4 + 8);
            qf[ks][3] = ldh2(bp + 8 * KSTR + ks * 16 + 2 * t4 + 8);
        }
    }
    __syncthreads();

    float o[16][4];
    #pragma unroll
    for (int j = 0; j < 16; j++) { o[j][0] = o[j][1] = o[j][2] = o[j][3] = 0.f; }
    float m0 = -1e30f, m1 = -1e30f, l0 = 0.f, l1 = 0.f;
    const float KS2 = 0.08838834764831845f * 1.4426950408889634f;  // 1/sqrt(d)*log2e

    auto issue = [&](int kt) {
        const int b = kt & (FNST - 1);
        const __half* Kg = Kg0 + (size_t)(kt * 64) * Dm;
        __half* Kd = Ks + b * 64 * KSTR;
        __half* Vd = Vs + b * 128 * VSTR;
        #pragma unroll
        for (int i = 0; i < 4; i++) {
            int idx = t + i * 256;                 // 1024 K chunks (64 rows x 16)
            int r = idx >> 4, c = idx & 15;
            cp16(Kd + r * KSTR + c * 8, Kg + (size_t)r * Dm + c * 8);
        }
        #pragma unroll
        for (int i = 0; i < 4; i++) {
            int idx = t + i * 256;                 // 1024 Vt chunks (128 rows x 8)
            int r = idx >> 3, c = idx & 7;
            cp16(Vd + r * VSTR + c * 8, Vtg + (size_t)r * Lq + kt * 64 + c * 8);
        }
        CP_COMMIT;
    };

    issue(0); issue(1);
    const int NT = Lq / 64;
    for (int kt = 0; kt < NT; kt++) {
        const int b = kt & (FNST - 1);
        if (kt + 2 < NT) { issue(kt + 2); CP_WAIT(2); }
        else if (kt + 1 < NT) { CP_WAIT(1); }
        else { CP_WAIT(0); }
        __syncthreads();   // single barrier: stage b visible; stage (kt+2)%4 safe (dist 3 from slowest reader)

        // S = Q @ K^T : 16 rows x 64 keys per warp
        float s[8][4];
        #pragma unroll
        for (int j = 0; j < 8; j++) { s[j][0] = s[j][1] = s[j][2] = s[j][3] = 0.f; }
        const __half* Kb = Ks + b * 64 * KSTR;
        #pragma unroll
        for (int ks = 0; ks < 8; ks++) {
            #pragma unroll
            for (int j = 0; j < 8; j++) {
                const __half* kp = Kb + (j * 8 + g) * KSTR + ks * 16 + 2 * t4;
                mma16(s[j], qf[ks], ldh2(kp), ldh2(kp + 8));
            }
        }

        // Online softmax (log2 domain); P packed to half2 fragments in regs
        float mx0 = -1e30f, mx1 = -1e30f;
        #pragma unroll
        for (int j = 0; j < 8; j++) {
            mx0 = fmaxf(mx0, fmaxf(s[j][0], s[j][1]));
            mx1 = fmaxf(mx1, fmaxf(s[j][2], s[j][3]));
        }
        mx0 *= KS2; mx1 *= KS2;
        mx0 = fmaxf(mx0, __shfl_xor_sync(0xffffffffu, mx0, 1));
        mx0 = fmaxf(mx0, __shfl_xor_sync(0xffffffffu, mx0, 2));
        mx1 = fmaxf(mx1, __shfl_xor_sync(0xffffffffu, mx1, 1));
        mx1 = fmaxf(mx1, __shfl_xor_sync(0xffffffffu, mx1, 2));
        float nm0 = fmaxf(m0, mx0), nm1 = fmaxf(m1, mx1);
        float corr0 = ex2f(m0 - nm0), corr1 = ex2f(m1 - nm1);
        m0 = nm0; m1 = nm1;
        float r0 = 0.f, r1 = 0.f;
        uint32_t ph[8][2];
        #pragma unroll
        for (int j = 0; j < 8; j++) {
            float p00 = ex2f(s[j][0] * KS2 - m0);
            float p01 = ex2f(s[j][1] * KS2 - m0);
            float p10 = ex2f(s[j][2] * KS2 - m1);
            float p11 = ex2f(s[j][3] * KS2 - m1);
            r0 += p00 + p01; r1 += p10 + p11;
            ph[j][0] = packh2(p00, p01);     // rows g,   keys j*8+2t4..
            ph[j][1] = packh2(p10, p11);     // rows g+8, keys j*8+2t4..
        }
        r0 += __shfl_xor_sync(0xffffffffu, r0, 1);
        r0 += __shfl_xor_sync(0xffffffffu, r0, 2);
        r1 += __shfl_xor_sync(0xffffffffu, r1, 1);
        r1 += __shfl_xor_sync(0xffffffffu, r1, 2);
        l0 = l0 * corr0 + r0;
        l1 = l1 * corr1 + r1;
        #pragma unroll
        for (int j = 0; j < 16; j++) {
            o[j][0] *= corr0; o[j][1] *= corr0;
            o[j][2] *= corr1; o[j][3] *= corr1;
        }

        // O += P @ V  directly from register P (A frag = repacked S frags)
        const __half* Vb = Vs + b * 128 * VSTR;
        #pragma unroll
        for (int mm = 0; mm < 4; mm++) {
            uint32_t a[4] = { ph[2 * mm][0], ph[2 * mm][1],
                              ph[2 * mm + 1][0], ph[2 * mm + 1][1] };
            #pragma unroll
            for (int j = 0; j < 16; j++) {
                const __half* vp = Vb + (j * 8 + g) * VSTR + mm * 16 + 2 * t4;
                mma16(o[j], a, ldh2(vp), ldh2(vp + 8));
            }
        }
    }

    const float inv0 = 1.f / l0, inv1 = 1.f / l1;
    __half* O0 = O + (size_t)(q0 + wid * 16 + g) * Dm + head * HDim + 2 * t4;
    __half* O1 = O0 + 8 * (size_t)Dm;
    #pragma unroll
    for (int j = 0; j < 16; j++) {
        *(__half2*)(O0 + j * 8) = __floats2half2_rn(o[j][0] * inv0, o[j][1] * inv0);
        *(__half2*)(O1 + j * 8) = __floats2half2_rn(o[j][2] * inv1, o[j][3] * inv1);
    }
}

// ---------------------------------------------------------------------------
// Launch
// ---------------------------------------------------------------------------
extern "C" void kernel_launch(void* const* d_in, const int* in_sizes, int n_in,
                              void* d_out, int out_size)
{
    const float* x    = (const float*)d_in[0];
    const float* wq   = (const float*)d_in[1];
    const float* wk   = (const float*)d_in[2];
    const float* wv   = (const float*)d_in[3];
    const float* wo   = (const float*)d_in[4];
    const float* bq   = (const float*)d_in[5];
    const float* bk   = (const float*)d_in[6];
    const float* bv   = (const float*)d_in[7];
    const float* bo   = (const float*)d_in[8];
    const float* gq   = (const float*)d_in[9];
    const float* gk   = (const float*)d_in[10];
    const float* fcos = (const float*)d_in[11];
    const float* fsin = (const float*)d_in[12];
    // d_in[13] = seq_lens (all == L)
    const int* pH = (const int*)d_in[15];
    const int* pW = (const int*)d_in[16];
    float* out = (float*)d_out;

    __half *Xh, *Wqh, *Wkh, *Wvh, *Woh, *Qh, *Kh, *Vh, *Vt, *Ah;
    cudaGetSymbolAddress((void**)&Xh, g_Xh);
    cudaGetSymbolAddress((void**)&Wqh, g_Wqh);
    cudaGetSymbolAddress((void**)&Wkh, g_Wkh);
    cudaGetSymbolAddress((void**)&Wvh, g_Wvh);
    cudaGetSymbolAddress((void**)&Woh, g_Woh);
    cudaGetSymbolAddress((void**)&Qh, g_Qh);
    cudaGetSymbolAddress((void**)&Kh, g_Kh);
    cudaGetSymbolAddress((void**)&Vh, g_Vh);
    cudaGetSymbolAddress((void**)&Vt, g_Vt);
    cudaGetSymbolAddress((void**)&Ah, g_Ah);

    cudaFuncSetAttribute(gemm_h, cudaFuncAttributeMaxDynamicSharedMemorySize, G_SMEM);
    cudaFuncSetAttribute(flash_h, cudaFuncAttributeMaxDynamicSharedMemorySize, FL_SMEM);

    const int nX = Lq * Dm, nW = Dm * Dm;
    to_half<<<nX / 8 / 256, 256>>>(x, Xh, nX);
    to_half4<<<dim3(nW / 8 / 256, 4), 256>>>(wq, wk, wv, wo, Wqh, Wkh, Wvh, Woh, nW);

    dim3 gg(Dm / 128, Lq / 128);
    gemm_h<<<gg, 256, G_SMEM>>>(Xh, Wqh, bq, Qh, 1);
    gemm_h<<<gg, 256, G_SMEM>>>(Xh, Wkh, bk, Kh, 1);
    gemm_h<<<gg, 256, G_SMEM>>>(Xh, Wvh, bv, Vh, 1);

    rmsnorm_rope_h<<<dim3(Lq, 2), 256>>>(Qh, Kh, gq, gk, fcos, fsin, pH, pW);

    transpose_v<<<dim3(Lq / 32, Dm / 32), 256>>>(Vh, Vt);

    flash_h<<<dim3(Lq / 128, NH), 256, FL_SMEM>>>(Qh, Kh, Vt, Ah);

    gemm_h<<<gg, 256, G_SMEM>>>(Ah, Woh, bo, out, 0);
}

// round 7
// speedup vs baseline: 9.3731x; 1.1320x over previous
#include <cuda_runtime.h>
#include <cuda_fp16.h>
#include <math.h>
#include <stdint.h>

// Problem constants (fixed shapes)
#define Lq 4096
#define Dm 1536
#define NH 12
#define HDim 128
#define Cc 64
#define S1c 22
#define S2c 21
#define EPSF 1e-6f

// Scratch (device globals; no runtime allocation allowed)
__device__ __half g_Xh[Lq * Dm];
__device__ __half g_Wc[3 * Dm * Dm];   // Wq | Wk | Wv concatenated along rows
__device__ __half g_Woh[Dm * Dm];
__device__ __half g_Qh[Lq * Dm];
__device__ __half g_Kh[Lq * Dm];
__device__ __half g_Vh[Lq * Dm];
__device__ __half g_Vt[Dm * Lq];       // [d_global][token]
__device__ __half g_Ah[Lq * Dm];

// ---------------------------------------------------------------------------
// Helpers
// ---------------------------------------------------------------------------
__device__ __forceinline__ float ex2f(float x) {
    float y;
    asm("ex2.approx.ftz.f32 %0, %1;" : "=f"(y) : "f"(x));
    return y;
}

__device__ __forceinline__ void mma16(float* c, const uint32_t* a, uint32_t b0, uint32_t b1) {
    asm volatile(
        "mma.sync.aligned.m16n8k16.row.col.f32.f16.f16.f32 "
        "{%0,%1,%2,%3}, {%4,%5,%6,%7}, {%8,%9}, {%0,%1,%2,%3};\n"
        : "+f"(c[0]), "+f"(c[1]), "+f"(c[2]), "+f"(c[3])
        : "r"(a[0]), "r"(a[1]), "r"(a[2]), "r"(a[3]), "r"(b0), "r"(b1));
}

__device__ __forceinline__ void ldsm4(uint32_t& r0, uint32_t& r1, uint32_t& r2,
                                      uint32_t& r3, uint32_t a) {
    asm volatile("ldmatrix.sync.aligned.m8n8.x4.shared.b16 {%0,%1,%2,%3}, [%4];"
                 : "=r"(r0), "=r"(r1), "=r"(r2), "=r"(r3) : "r"(a));
}

__device__ __forceinline__ void cp16(const void* dst_smem, const void* src) {
    uint32_t d = (uint32_t)__cvta_generic_to_shared(dst_smem);
    asm volatile("cp.async.cg.shared.global [%0], [%1], 16;\n" :: "r"(d), "l"(src));
}
#define CP_COMMIT asm volatile("cp.async.commit_group;\n")
#define CP_WAIT(n) asm volatile("cp.async.wait_group %0;\n" :: "n"(n))

__device__ __forceinline__ uint32_t smem_u32(const void* p) {
    return (uint32_t)__cvta_generic_to_shared(p);
}
__device__ __forceinline__ uint32_t ldh2(const __half* p) { return *(const uint32_t*)p; }
__device__ __forceinline__ uint32_t packh2(float a, float b) {
    __half2 h = __floats2half2_rn(a, b);
    return *(uint32_t*)&h;
}

// ---------------------------------------------------------------------------
// fp32 -> fp16 conversion pre-passes
// ---------------------------------------------------------------------------
__global__ __launch_bounds__(256) void to_half(const float* __restrict__ in,
                                               __half* __restrict__ out, int n) {
    int i = (blockIdx.x * 256 + threadIdx.x) * 8;
    if (i < n) {
        float4 v0 = *(const float4*)(in + i);
        float4 v1 = *(const float4*)(in + i + 4);
        uint4 pk;
        pk.x = packh2(v0.x, v0.y); pk.y = packh2(v0.z, v0.w);
        pk.z = packh2(v1.x, v1.y); pk.w = packh2(v1.z, v1.w);
        *(uint4*)(out + i) = pk;
    }
}

__global__ __launch_bounds__(256) void to_half4(
    const float* __restrict__ w0, const float* __restrict__ w1,
    const float* __restrict__ w2, const float* __restrict__ w3,
    __half* __restrict__ o0, __half* __restrict__ o1,
    __half* __restrict__ o2, __half* __restrict__ o3, int n)
{
    const float* in; __half* out;
    switch (blockIdx.y) {
        case 0: in = w0; out = o0; break;
        case 1: in = w1; out = o1; break;
        case 2: in = w2; out = o2; break;
        default: in = w3; out = o3; break;
    }
    int i = (blockIdx.x * 256 + threadIdx.x) * 8;
    if (i < n) {
        float4 v0 = *(const float4*)(in + i);
        float4 v1 = *(const float4*)(in + i + 4);
        uint4 pk;
        pk.x = packh2(v0.x, v0.y); pk.y = packh2(v0.z, v0.w);
        pk.z = packh2(v1.x, v1.y); pk.w = packh2(v1.z, v1.w);
        *(uint4*)(out + i) = pk;
    }
}

// ---------------------------------------------------------------------------
// fp16 GEMM core: C[.., ncol0..ncol0+128) = X[m0..,K] @ Wr[0..128,K]^T + bias
// BM=BN=128, BK=32, 8 warps (4m x 2n), warp tile 32x64. ldmatrix fragment loads.
// ---------------------------------------------------------------------------
#define GSTR 40
#define GTILE (128 * GSTR)
#define GSTAGE (2 * GTILE)
#define NSTG 5
#define G_SMEM (NSTG * GSTAGE * 2)

__device__ __forceinline__ void gemm_body(
    const __half* __restrict__ X, const __half* __restrict__ Wr,
    const float* __restrict__ bias, void* __restrict__ Cout, int outHalf,
    int m0, int ncol0, __half* smg)
{
    const uint32_t sbase = smem_u32(smg);
    const int t = threadIdx.x, lane = t & 31, wid = t >> 5;
    const int g = lane >> 2, t4 = lane & 3;
    const int wm = wid >> 1, wn = wid & 1;

    float acc[2][8][4];
    #pragma unroll
    for (int i = 0; i < 2; i++)
        #pragma unroll
        for (int j = 0; j < 8; j++)
            #pragma unroll
            for (int q = 0; q < 4; q++) acc[i][j][q] = 0.f;

    auto issue = [&](int kt) {
        __half* As = smg + (kt % NSTG) * GSTAGE;
        __half* Bs = As + GTILE;
        const int k0 = kt * 32;
        #pragma unroll
        for (int i = 0; i < 2; i++) {
            int idx = t + i * 256;
            int r = idx >> 2, c = idx & 3;
            cp16(As + r * GSTR + c * 8, X + (size_t)(m0 + r) * Dm + k0 + c * 8);
        }
        #pragma unroll
        for (int i = 0; i < 2; i++) {
            int idx = t + i * 256;
            int r = idx >> 2, c = idx & 3;
            cp16(Bs + r * GSTR + c * 8, Wr + (size_t)r * Dm + k0 + c * 8);
        }
        CP_COMMIT;
    };

    issue(0); issue(1); issue(2); issue(3);

    // ldmatrix per-lane offsets (bytes)
    const uint32_t aOff =
        (uint32_t)(((wm * 32 + (lane & 7) + ((lane >> 3) & 1) * 8) * GSTR +
                    (lane >> 4) * 8) * 2);
    const uint32_t bOff =
        (uint32_t)(((wn * 64 + (lane & 7) + (lane >> 4) * 8) * GSTR +
                    ((lane >> 3) & 1) * 8) * 2);

    const int KT = Dm / 32;
    for (int kt = 0; kt < KT; kt++) {
        CP_WAIT(3);
        __syncthreads();
        const uint32_t stA = sbase + (uint32_t)((kt % NSTG) * GSTAGE * 2);
        const uint32_t stB = stA + GTILE * 2;
        #pragma unroll
        for (int ks = 0; ks < 2; ks++) {
            uint32_t af[2][4], bf[8][2];
            ldsm4(af[0][0], af[0][1], af[0][2], af[0][3], stA + aOff + ks * 32);
            ldsm4(af[1][0], af[1][1], af[1][2], af[1][3],
                  stA + aOff + 16 * GSTR * 2 + ks * 32);
            #pragma unroll
            for (int jj = 0; jj < 4; jj++)
                ldsm4(bf[2 * jj][0], bf[2 * jj][1], bf[2 * jj + 1][0], bf[2 * jj + 1][1],
                      stB + bOff + jj * 16 * GSTR * 2 + ks * 32);
            #pragma unroll
            for (int i = 0; i < 2; i++)
                #pragma unroll
                for (int j = 0; j < 8; j++)
                    mma16(acc[i][j], af[i], bf[j][0], bf[j][1]);
        }
        __syncthreads();
        if (kt + 4 < KT) issue(kt + 4);
    }

    #pragma unroll
    for (int j = 0; j < 8; j++) {
        int lc = wn * 64 + j * 8 + 2 * t4;
        float b0 = bias[lc], b1 = bias[lc + 1];
        int col = ncol0 + lc;
        #pragma unroll
        for (int i = 0; i < 2; i++) {
            int row = m0 + wm * 32 + i * 16 + g;
            float c00 = acc[i][j][0] + b0, c01 = acc[i][j][1] + b1;
            float c10 = acc[i][j][2] + b0, c11 = acc[i][j][3] + b1;
            if (outHalf) {
                __half* C = (__half*)Cout;
                *(__half2*)(C + (size_t)row * Dm + col) = __floats2half2_rn(c00, c01);
                *(__half2*)(C + (size_t)(row + 8) * Dm + col) = __floats2half2_rn(c10, c11);
            } else {
                float* C = (float*)Cout;
                *(float2*)(C + (size_t)row * Dm + col) = make_float2(c00, c01);
                *(float2*)(C + (size_t)(row + 8) * Dm + col) = make_float2(c10, c11);
            }
        }
    }
}

// Fused QKV: grid (3*Dm/128, Lq/128); n-tile picks tensor segment.
__global__ __launch_bounds__(256, 2) void gemm_qkv(
    const __half* __restrict__ X, const __half* __restrict__ Wc,
    const float* __restrict__ bq, const float* __restrict__ bk,
    const float* __restrict__ bv,
    __half* __restrict__ Qh, __half* __restrict__ Kh, __half* __restrict__ Vh)
{
    extern __shared__ __half smg[];
    const int n0g = blockIdx.x * 128;
    const int seg = n0g / Dm;
    const int n0 = n0g - seg * Dm;
    const float* bias = (seg == 0) ? bq : (seg == 1) ? bk : bv;
    __half* C = (seg == 0) ? Qh : (seg == 1) ? Kh : Vh;
    gemm_body(X, Wc + (size_t)n0g * Dm, bias + n0, C, 1,
              blockIdx.y * 128, n0, smg);
}

// Output projection (fp32 out)
__global__ __launch_bounds__(256, 2) void gemm_o(
    const __half* __restrict__ X, const __half* __restrict__ W,
    const float* __restrict__ bias, float* __restrict__ out)
{
    extern __shared__ __half smg[];
    const int n0 = blockIdx.x * 128;
    gemm_body(X, W + (size_t)n0 * Dm, bias + n0, out, 0, blockIdx.y * 128, n0, smg);
}

// ---------------------------------------------------------------------------
// RMSNorm + 3D RoPE on Q and K (grid.y = 0: Q, 1: K)
// ---------------------------------------------------------------------------
__global__ __launch_bounds__(256) void rmsnorm_rope_h(
    __half* __restrict__ Tq, __half* __restrict__ Tk,
    const float* __restrict__ gqv, const float* __restrict__ gkv,
    const float* __restrict__ fcos, const float* __restrict__ fsin,
    const int* __restrict__ pH, const int* __restrict__ pW)
{
    __half* T = blockIdx.y ? Tk : Tq;
    const float* g = blockIdx.y ? gkv : gqv;
    const int row = blockIdx.x;
    __half* p = T + (size_t)row * Dm;

    float ss = 0.f;
    for (int i = threadIdx.x * 2; i < Dm; i += 512) {
        float2 v = __half22float2(*(const __half2*)(p + i));
        ss += v.x * v.x + v.y * v.y;
    }
    __shared__ float red[8];
    const int lane = threadIdx.x & 31;
    const int wid = threadIdx.x >> 5;
    #pragma unroll
    for (int off = 16; off >= 1; off >>= 1)
        ss += __shfl_xor_sync(0xffffffffu, ss, off);
    if (lane == 0) red[wid] = ss;
    __syncthreads();
    if (wid == 0) {
        float v = (lane < 8) ? red[lane] : 0.f;
        #pragma unroll
        for (int off = 4; off >= 1; off >>= 1)
            v += __shfl_xor_sync(0xffffffffu, v, off);
        if (lane == 0) red[0] = rsqrtf(v * (1.f / Dm) + EPSF);
    }
    __syncthreads();
    const float rms = red[0];

    const int H = *pH, W = *pW;
    const int f = row / (H * W);
    const int hh = (row / W) % H;
    const int ww = row % W;

    for (int pj = threadIdx.x; pj < NH * Cc; pj += 256) {
        const int n = pj / Cc;
        const int j = pj % Cc;
        const int coord = (j < S1c) ? f : ((j < S1c + S2c) ? hh : ww);
        const float ccos = fcos[coord * Cc + j];
        const float csin = fsin[coord * Cc + j];
        const int idx = n * HDim + 2 * j;
        float2 v = __half22float2(*(const __half2*)(p + idx));
        const float xr = v.x * rms * g[idx];
        const float xi = v.y * rms * g[idx + 1];
        *(__half2*)(p + idx) = __floats2half2_rn(xr * ccos - xi * csin,
                                                 xr * csin + xi * ccos);
    }
}

// ---------------------------------------------------------------------------
// Transpose V: Vh[token][dglobal] -> Vt[dglobal][token]
// ---------------------------------------------------------------------------
__global__ __launch_bounds__(256) void transpose_v(const __half* __restrict__ Vh,
                                                   __half* __restrict__ Vt)
{
    __shared__ __half tile[32][33];
    const int tx = threadIdx.x & 31, ty = threadIdx.x >> 5;
    const int t0 = blockIdx.x * 32;
    const int d0 = blockIdx.y * 32;
    #pragma unroll
    for (int i = 0; i < 4; i++)
        tile[ty + i * 8][tx] = Vh[(size_t)(t0 + ty + i * 8) * Dm + d0 + tx];
    __syncthreads();
    #pragma unroll
    for (int i = 0; i < 4; i++)
        Vt[(size_t)(d0 + ty + i * 8) * Lq + t0 + tx] = tile[tx][ty + i * 8];
}

// ---------------------------------------------------------------------------
// Flash attention, fp16 mma, ldmatrix loads. BQ=128, key tile 64.
// P in registers; 4-stage cp.async ring, one barrier/iter.
// ---------------------------------------------------------------------------
#define KSTR 136
#define VSTR 72
#define FNST 4
#define FL_SMEM ((FNST * 64 * KSTR + FNST * 128 * VSTR) * 2)

__global__ __launch_bounds__(256, 1) void flash_h(
    const __half* __restrict__ Q, const __half* __restrict__ K,
    const __half* __restrict__ Vt, __half* __restrict__ O)
{
    extern __shared__ __half smf[];
    __half* Ks = smf;
    __half* Vs = Ks + FNST * 64 * KSTR;
    const uint32_t sB = smem_u32(smf);

    const int t = threadIdx.x, lane = t & 31, wid = t >> 5;
    const int g = lane >> 2, t4 = lane & 3;
    const int head = blockIdx.y;
    const int q0 = blockIdx.x * 128;
    const __half* Qg = Q + (size_t)q0 * Dm + head * HDim;
    const __half* Kg0 = K + head * HDim;
    const __half* Vtg = Vt + (size_t)(head * HDim) * Lq;

    for (int i = t; i < 128 * 16; i += 256) {
        int r = i >> 4, c = i & 15;
        *(uint4*)(Ks + r * KSTR + c * 8) = *(const uint4*)(Qg + (size_t)r * Dm + c * 8);
    }
    __syncthreads();
    uint32_t qf[8][4];
    {
        const __half* bp = Ks + (wid * 16 + g) * KSTR;
        #pragma unroll
        for (int ks = 0; ks < 8; ks++) {
            qf[ks][0] = ldh2(bp + ks * 16 + 2 * t4);
            qf[ks][1] = ldh2(bp + 8 * KSTR + ks * 16 + 2 * t4);
            qf[ks][2] = ldh2(bp + ks * 16 + 2 * t4 + 8);
            qf[ks][3] = ldh2(bp + 8 * KSTR + ks * 16 + 2 * t4 + 8);
        }
    }
    __syncthreads();

    float o[16][4];
    #pragma unroll
    for (int j = 0; j < 16; j++) { o[j][0] = o[j][1] = o[j][2] = o[j][3] = 0.f; }
    float m0 = -1e30f, m1 = -1e30f, l0 = 0.f, l1 = 0.f;
    const float KS2 = 0.08838834764831845f * 1.4426950408889634f;

    auto issue = [&](int kt) {
        const int b = kt & (FNST - 1);
        const __half* Kg = Kg0 + (size_t)(kt * 64) * Dm;
        __half* Kd = Ks + b * 64 * KSTR;
        __half* Vd = Vs + b * 128 * VSTR;
        #pragma unroll
        for (int i = 0; i < 4; i++) {
            int idx = t + i * 256;
            int r = idx >> 4, c = idx & 15;
            cp16(Kd + r * KSTR + c * 8, Kg + (size_t)r * Dm + c * 8);
        }
        #pragma unroll
        for (int i = 0; i < 4; i++) {
            int idx = t + i * 256;
            int r = idx >> 3, c = idx & 7;
            cp16(Vd + r * VSTR + c * 8, Vtg + (size_t)r * Lq + kt * 64 + c * 8);
        }
        CP_COMMIT;
    };

    // ldmatrix per-lane offsets (bytes)
    const uint32_t kOff =
        (uint32_t)((((lane & 7) + (lane >> 4) * 8) * KSTR + ((lane >> 3) & 1) * 8) * 2);
    const uint32_t vOff =
        (uint32_t)((((lane & 7) + (lane >> 4) * 8) * VSTR + ((lane >> 3) & 1) * 8) * 2);

    issue(0); issue(1);
    const int NT = Lq / 64;
    for (int kt = 0; kt < NT; kt++) {
        const int b = kt & (FNST - 1);
        if (kt + 2 < NT) { issue(kt + 2); CP_WAIT(2); }
        else if (kt + 1 < NT) { CP_WAIT(1); }
        else { CP_WAIT(0); }
        __syncthreads();

        const uint32_t stK = sB + (uint32_t)(b * 64 * KSTR * 2);
        const uint32_t stV = sB + (uint32_t)((FNST * 64 * KSTR + b * 128 * VSTR) * 2);

        // S = Q @ K^T
        float s[8][4];
        #pragma unroll
        for (int j = 0; j < 8; j++) { s[j][0] = s[j][1] = s[j][2] = s[j][3] = 0.f; }
        #pragma unroll
        for (int ks = 0; ks < 8; ks++) {
            uint32_t kf[8][2];
            #pragma unroll
            for (int jj = 0; jj < 4; jj++)
                ldsm4(kf[2 * jj][0], kf[2 * jj][1], kf[2 * jj + 1][0], kf[2 * jj + 1][1],
                      stK + kOff + jj * 16 * KSTR * 2 + ks * 32);
            #pragma unroll
            for (int j = 0; j < 8; j++)
                mma16(s[j], qf[ks], kf[j][0], kf[j][1]);
        }

        // Online softmax; P packed to register fragments
        float mx0 = -1e30f, mx1 = -1e30f;
        #pragma unroll
        for (int j = 0; j < 8; j++) {
            mx0 = fmaxf(mx0, fmaxf(s[j][0], s[j][1]));
            mx1 = fmaxf(mx1, fmaxf(s[j][2], s[j][3]));
        }
        mx0 *= KS2; mx1 *= KS2;
        mx0 = fmaxf(mx0, __shfl_xor_sync(0xffffffffu, mx0, 1));
        mx0 = fmaxf(mx0, __shfl_xor_sync(0xffffffffu, mx0, 2));
        mx1 = fmaxf(mx1, __shfl_xor_sync(0xffffffffu, mx1, 1));
        mx1 = fmaxf(mx1, __shfl_xor_sync(0xffffffffu, mx1, 2));
        float nm0 = fmaxf(m0, mx0), nm1 = fmaxf(m1, mx1);
        float corr0 = ex2f(m0 - nm0), corr1 = ex2f(m1 - nm1);
        m0 = nm0; m1 = nm1;
        float r0 = 0.f, r1 = 0.f;
        uint32_t ph[8][2];
        #pragma unroll
        for (int j = 0; j < 8; j++) {
            float p00 = ex2f(s[j][0] * KS2 - m0);
            float p01 = ex2f(s[j][1] * KS2 - m0);
            float p10 = ex2f(s[j][2] * KS2 - m1);
            float p11 = ex2f(s[j][3] * KS2 - m1);
            r0 += p00 + p01; r1 += p10 + p11;
            ph[j][0] = packh2(p00, p01);
            ph[j][1] = packh2(p10, p11);
        }
        r0 += __shfl_xor_sync(0xffffffffu, r0, 1);
        r0 += __shfl_xor_sync(0xffffffffu, r0, 2);
        r1 += __shfl_xor_sync(0xffffffffu, r1, 1);
        r1 += __shfl_xor_sync(0xffffffffu, r1, 2);
        l0 = l0 * corr0 + r0;
        l1 = l1 * corr1 + r1;
        #pragma unroll
        for (int j = 0; j < 16; j++) {
            o[j][0] *= corr0; o[j][1] *= corr0;
            o[j][2] *= corr1; o[j][3] *= corr1;
        }

        // O += P @ V
        #pragma unroll
        for (int mm = 0; mm < 4; mm++) {
            uint32_t a[4] = { ph[2 * mm][0], ph[2 * mm][1],
                              ph[2 * mm + 1][0], ph[2 * mm + 1][1] };
            #pragma unroll
            for (int jj = 0; jj < 8; jj++) {
                uint32_t v0, v1, v2, v3;
                ldsm4(v0, v1, v2, v3, stV + vOff + jj * 16 * VSTR * 2 + mm * 32);
                mma16(o[2 * jj], a, v0, v1);
                mma16(o[2 * jj + 1], a, v2, v3);
            }
        }
    }

    const float inv0 = 1.f / l0, inv1 = 1.f / l1;
    __half* O0 = O + (size_t)(q0 + wid * 16 + g) * Dm + head * HDim + 2 * t4;
    __half* O1 = O0 + 8 * (size_t)Dm;
    #pragma unroll
    for (int j = 0; j < 16; j++) {
        *(__half2*)(O0 + j * 8) = __floats2half2_rn(o[j][0] * inv0, o[j][1] * inv0);
        *(__half2*)(O1 + j * 8) = __floats2half2_rn(o[j][2] * inv1, o[j][3] * inv1);
    }
}

// ---------------------------------------------------------------------------
// Launch
// ---------------------------------------------------------------------------
extern "C" void kernel_launch(void* const* d_in, const int* in_sizes, int n_in,
                              void* d_out, int out_size)
{
    const float* x    = (const float*)d_in[0];
    const float* wq   = (const float*)d_in[1];
    const float* wk   = (const float*)d_in[2];
    const float* wv   = (const float*)d_in[3];
    const float* wo   = (const float*)d_in[4];
    const float* bq   = (const float*)d_in[5];
    const float* bk   = (const float*)d_in[6];
    const float* bv   = (const float*)d_in[7];
    const float* bo   = (const float*)d_in[8];
    const float* gq   = (const float*)d_in[9];
    const float* gk   = (const float*)d_in[10];
    const float* fcos = (const float*)d_in[11];
    const float* fsin = (const float*)d_in[12];
    // d_in[13] = seq_lens (all == L)
    const int* pH = (const int*)d_in[15];
    const int* pW = (const int*)d_in[16];
    float* out = (float*)d_out;

    __half *Xh, *Wc, *Woh, *Qh, *Kh, *Vh, *Vt, *Ah;
    cudaGetSymbolAddress((void**)&Xh, g_Xh);
    cudaGetSymbolAddress((void**)&Wc, g_Wc);
    cudaGetSymbolAddress((void**)&Woh, g_Woh);
    cudaGetSymbolAddress((void**)&Qh, g_Qh);
    cudaGetSymbolAddress((void**)&Kh, g_Kh);
    cudaGetSymbolAddress((void**)&Vh, g_Vh);
    cudaGetSymbolAddress((void**)&Vt, g_Vt);
    cudaGetSymbolAddress((void**)&Ah, g_Ah);

    cudaFuncSetAttribute(gemm_qkv, cudaFuncAttributeMaxDynamicSharedMemorySize, G_SMEM);
    cudaFuncSetAttribute(gemm_o, cudaFuncAttributeMaxDynamicSharedMemorySize, G_SMEM);
    cudaFuncSetAttribute(flash_h, cudaFuncAttributeMaxDynamicSharedMemorySize, FL_SMEM);

    const int nX = Lq * Dm, nW = Dm * Dm;
    to_half<<<nX / 8 / 256, 256>>>(x, Xh, nX);
    to_half4<<<dim3(nW / 8 / 256, 4), 256>>>(wq, wk, wv, wo,
                                             Wc, Wc + (size_t)Dm * Dm,
                                             Wc + 2 * (size_t)Dm * Dm, Woh, nW);

    gemm_qkv<<<dim3(3 * Dm / 128, Lq / 128), 256, G_SMEM>>>(
        Xh, Wc, bq, bk, bv, Qh, Kh, Vh);

    rmsnorm_rope_h<<<dim3(Lq, 2), 256>>>(Qh, Kh, gq, gk, fcos, fsin, pH, pW);

    transpose_v<<<dim3(Lq / 32, Dm / 32), 256>>>(Vh, Vt);

    flash_h<<<dim3(Lq / 128, NH), 256, FL_SMEM>>>(Qh, Kh, Vt, Ah);

    gemm_o<<<dim3(Dm / 128, Lq / 128), 256, G_SMEM>>>(Ah, Woh, bo, out);
}

// round 8
// speedup vs baseline: 9.5318x; 1.0169x over previous
#include <cuda_runtime.h>
#include <cuda_fp16.h>
#include <math.h>
#include <stdint.h>

// Problem constants (fixed shapes)
#define Lq 4096
#define Dm 1536
#define NH 12
#define HDim 128
#define Cc 64
#define S1c 22
#define S2c 21
#define EPSF 1e-6f

// Scratch (device globals; no runtime allocation allowed)
__device__ __half g_Xh[Lq * Dm];
__device__ __half g_Wc[3 * Dm * Dm];   // Wq | Wk | Wv concatenated along rows
__device__ __half g_Woh[Dm * Dm];
__device__ __half g_Qh[Lq * Dm];
__device__ __half g_Kh[Lq * Dm];
__device__ __half g_Vt[Dm * Lq];       // [d_global][token]
__device__ __half g_Ah[Lq * Dm];

// ---------------------------------------------------------------------------
// Helpers
// ---------------------------------------------------------------------------
__device__ __forceinline__ float ex2f(float x) {
    float y;
    asm("ex2.approx.ftz.f32 %0, %1;" : "=f"(y) : "f"(x));
    return y;
}

__device__ __forceinline__ void mma16(float* c, const uint32_t* a, uint32_t b0, uint32_t b1) {
    asm volatile(
        "mma.sync.aligned.m16n8k16.row.col.f32.f16.f16.f32 "
        "{%0,%1,%2,%3}, {%4,%5,%6,%7}, {%8,%9}, {%0,%1,%2,%3};\n"
        : "+f"(c[0]), "+f"(c[1]), "+f"(c[2]), "+f"(c[3])
        : "r"(a[0]), "r"(a[1]), "r"(a[2]), "r"(a[3]), "r"(b0), "r"(b1));
}

__device__ __forceinline__ void ldsm4(uint32_t& r0, uint32_t& r1, uint32_t& r2,
                                      uint32_t& r3, uint32_t a) {
    asm volatile("ldmatrix.sync.aligned.m8n8.x4.shared.b16 {%0,%1,%2,%3}, [%4];"
                 : "=r"(r0), "=r"(r1), "=r"(r2), "=r"(r3) : "r"(a));
}

__device__ __forceinline__ void cp16(const void* dst_smem, const void* src) {
    uint32_t d = (uint32_t)__cvta_generic_to_shared(dst_smem);
    asm volatile("cp.async.cg.shared.global [%0], [%1], 16;\n" :: "r"(d), "l"(src));
}
#define CP_COMMIT asm volatile("cp.async.commit_group;\n")
#define CP_WAIT(n) asm volatile("cp.async.wait_group %0;\n" :: "n"(n))

__device__ __forceinline__ uint32_t smem_u32(const void* p) {
    return (uint32_t)__cvta_generic_to_shared(p);
}
__device__ __forceinline__ uint32_t ldh2(const __half* p) { return *(const uint32_t*)p; }
__device__ __forceinline__ uint32_t packh2(float a, float b) {
    __half2 h = __floats2half2_rn(a, b);
    return *(uint32_t*)&h;
}

// ---------------------------------------------------------------------------
// fp32 -> fp16 conversion pre-passes
// ---------------------------------------------------------------------------
__global__ __launch_bounds__(256) void to_half(const float* __restrict__ in,
                                               __half* __restrict__ out, int n) {
    int i = (blockIdx.x * 256 + threadIdx.x) * 8;
    if (i < n) {
        float4 v0 = *(const float4*)(in + i);
        float4 v1 = *(const float4*)(in + i + 4);
        uint4 pk;
        pk.x = packh2(v0.x, v0.y); pk.y = packh2(v0.z, v0.w);
        pk.z = packh2(v1.x, v1.y); pk.w = packh2(v1.z, v1.w);
        *(uint4*)(out + i) = pk;
    }
}

__global__ __launch_bounds__(256) void to_half4(
    const float* __restrict__ w0, const float* __restrict__ w1,
    const float* __restrict__ w2, const float* __restrict__ w3,
    __half* __restrict__ o0, __half* __restrict__ o1,
    __half* __restrict__ o2, __half* __restrict__ o3, int n)
{
    const float* in; __half* out;
    switch (blockIdx.y) {
        case 0: in = w0; out = o0; break;
        case 1: in = w1; out = o1; break;
        case 2: in = w2; out = o2; break;
        default: in = w3; out = o3; break;
    }
    int i = (blockIdx.x * 256 + threadIdx.x) * 8;
    if (i < n) {
        float4 v0 = *(const float4*)(in + i);
        float4 v1 = *(const float4*)(in + i + 4);
        uint4 pk;
        pk.x = packh2(v0.x, v0.y); pk.y = packh2(v0.z, v0.w);
        pk.z = packh2(v1.x, v1.y); pk.w = packh2(v1.z, v1.w);
        *(uint4*)(out + i) = pk;
    }
}

// ---------------------------------------------------------------------------
// fp16 GEMM core. mode 0: fp32 row-major out. mode 1: fp16 row-major out.
// mode 2: fp16 TRANSPOSED out to Vt[d][token] (via smem tile restage).
// BM=BN=128, BK=32, 8 warps (4m x 2n), ldmatrix fragment loads, 5-stage ring.
// ---------------------------------------------------------------------------
#define GSTR 40
#define GTILE (128 * GSTR)
#define GSTAGE (2 * GTILE)
#define NSTG 5
#define G_SMEM (NSTG * GSTAGE * 2)
#define TSTR 136   // transpose-stage stride (halfs): 272B = 17*16B

__device__ __forceinline__ void gemm_body(
    const __half* __restrict__ X, const __half* __restrict__ Wr,
    const float* __restrict__ bias, void* __restrict__ Cout, int mode,
    int m0, int ncol0, __half* smg, __half* __restrict__ VtOut)
{
    const uint32_t sbase = smem_u32(smg);
    const int t = threadIdx.x, lane = t & 31, wid = t >> 5;
    const int g = lane >> 2, t4 = lane & 3;
    const int wm = wid >> 1, wn = wid & 1;

    float acc[2][8][4];
    #pragma unroll
    for (int i = 0; i < 2; i++)
        #pragma unroll
        for (int j = 0; j < 8; j++)
            #pragma unroll
            for (int q = 0; q < 4; q++) acc[i][j][q] = 0.f;

    auto issue = [&](int kt) {
        __half* As = smg + (kt % NSTG) * GSTAGE;
        __half* Bs = As + GTILE;
        const int k0 = kt * 32;
        #pragma unroll
        for (int i = 0; i < 2; i++) {
            int idx = t + i * 256;
            int r = idx >> 2, c = idx & 3;
            cp16(As + r * GSTR + c * 8, X + (size_t)(m0 + r) * Dm + k0 + c * 8);
        }
        #pragma unroll
        for (int i = 0; i < 2; i++) {
            int idx = t + i * 256;
            int r = idx >> 2, c = idx & 3;
            cp16(Bs + r * GSTR + c * 8, Wr + (size_t)r * Dm + k0 + c * 8);
        }
        CP_COMMIT;
    };

    issue(0); issue(1); issue(2); issue(3);

    const uint32_t aOff =
        (uint32_t)(((wm * 32 + (lane & 7) + ((lane >> 3) & 1) * 8) * GSTR +
                    (lane >> 4) * 8) * 2);
    const uint32_t bOff =
        (uint32_t)(((wn * 64 + (lane & 7) + (lane >> 4) * 8) * GSTR +
                    ((lane >> 3) & 1) * 8) * 2);

    const int KT = Dm / 32;
    for (int kt = 0; kt < KT; kt++) {
        CP_WAIT(3);
        __syncthreads();
        const uint32_t stA = sbase + (uint32_t)((kt % NSTG) * GSTAGE * 2);
        const uint32_t stB = stA + GTILE * 2;
        #pragma unroll
        for (int ks = 0; ks < 2; ks++) {
            uint32_t af[2][4], bf[8][2];
            ldsm4(af[0][0], af[0][1], af[0][2], af[0][3], stA + aOff + ks * 32);
            ldsm4(af[1][0], af[1][1], af[1][2], af[1][3],
                  stA + aOff + 16 * GSTR * 2 + ks * 32);
            #pragma unroll
            for (int jj = 0; jj < 4; jj++)
                ldsm4(bf[2 * jj][0], bf[2 * jj][1], bf[2 * jj + 1][0], bf[2 * jj + 1][1],
                      stB + bOff + jj * 16 * GSTR * 2 + ks * 32);
            #pragma unroll
            for (int i = 0; i < 2; i++)
                #pragma unroll
                for (int j = 0; j < 8; j++)
                    mma16(acc[i][j], af[i], bf[j][0], bf[j][1]);
        }
        __syncthreads();
        if (kt + 4 < KT) issue(kt + 4);
    }

    if (mode == 2) {
        // Transposed epilogue: restage tile as [col][row] in smem, stream to Vt.
        __syncthreads();
        __half* Ts = smg;   // 128 * TSTR halfs = 34.8 KB, fits in stage area
        #pragma unroll
        for (int j = 0; j < 8; j++) {
            int lc = wn * 64 + j * 8 + 2 * t4;
            float b0 = bias[lc], b1 = bias[lc + 1];
            #pragma unroll
            for (int i = 0; i < 2; i++) {
                int r = wm * 32 + i * 16 + g;
                Ts[lc * TSTR + r]           = __float2half_rn(acc[i][j][0] + b0);
                Ts[(lc + 1) * TSTR + r]     = __float2half_rn(acc[i][j][1] + b1);
                Ts[lc * TSTR + r + 8]       = __float2half_rn(acc[i][j][2] + b0);
                Ts[(lc + 1) * TSTR + r + 8] = __float2half_rn(acc[i][j][3] + b1);
            }
        }
        __syncthreads();
        #pragma unroll
        for (int i = 0; i < 8; i++) {
            int idx = t + i * 256;          // 2048 chunks: 128 cols x 16
            int c = idx >> 4, ch = idx & 15;
            *(uint4*)(VtOut + (size_t)(ncol0 + c) * Lq + m0 + ch * 8) =
                *(const uint4*)(Ts + c * TSTR + ch * 8);
        }
        return;
    }

    #pragma unroll
    for (int j = 0; j < 8; j++) {
        int lc = wn * 64 + j * 8 + 2 * t4;
        float b0 = bias[lc], b1 = bias[lc + 1];
        int col = ncol0 + lc;
        #pragma unroll
        for (int i = 0; i < 2; i++) {
            int row = m0 + wm * 32 + i * 16 + g;
            float c00 = acc[i][j][0] + b0, c01 = acc[i][j][1] + b1;
            float c10 = acc[i][j][2] + b0, c11 = acc[i][j][3] + b1;
            if (mode == 1) {
                __half* C = (__half*)Cout;
                *(__half2*)(C + (size_t)row * Dm + col) = __floats2half2_rn(c00, c01);
                *(__half2*)(C + (size_t)(row + 8) * Dm + col) = __floats2half2_rn(c10, c11);
            } else {
                float* C = (float*)Cout;
                *(float2*)(C + (size_t)row * Dm + col) = make_float2(c00, c01);
                *(float2*)(C + (size_t)(row + 8) * Dm + col) = make_float2(c10, c11);
            }
        }
    }
}

// Fused QKV: grid (3*Dm/128, Lq/128). V segment written transposed to Vt.
__global__ __launch_bounds__(256, 2) void gemm_qkv(
    const __half* __restrict__ X, const __half* __restrict__ Wc,
    const float* __restrict__ bq, const float* __restrict__ bk,
    const float* __restrict__ bv,
    __half* __restrict__ Qh, __half* __restrict__ Kh, __half* __restrict__ Vt)
{
    extern __shared__ __half smg[];
    const int n0g = blockIdx.x * 128;
    const int seg = n0g / Dm;
    const int n0 = n0g - seg * Dm;
    const float* bias = (seg == 0) ? bq : (seg == 1) ? bk : bv;
    if (seg < 2) {
        gemm_body(X, Wc + (size_t)n0g * Dm, bias + n0, seg ? Kh : Qh, 1,
                  blockIdx.y * 128, n0, smg, nullptr);
    } else {
        gemm_body(X, Wc + (size_t)n0g * Dm, bias + n0, nullptr, 2,
                  blockIdx.y * 128, n0, smg, Vt);
    }
}

// Output projection (fp32 out)
__global__ __launch_bounds__(256, 2) void gemm_o(
    const __half* __restrict__ X, const __half* __restrict__ W,
    const float* __restrict__ bias, float* __restrict__ out)
{
    extern __shared__ __half smg[];
    const int n0 = blockIdx.x * 128;
    gemm_body(X, W + (size_t)n0 * Dm, bias + n0, out, 0, blockIdx.y * 128, n0,
              smg, nullptr);
}

// ---------------------------------------------------------------------------
// Single-pass RMSNorm + 3D RoPE on Q and K (grid.y = 0: Q, 1: K).
// Each thread holds its 3 complex pairs (6 halfs) in registers.
// ---------------------------------------------------------------------------
__global__ __launch_bounds__(256) void rmsnorm_rope_h(
    __half* __restrict__ Tq, __half* __restrict__ Tk,
    const float* __restrict__ gqv, const float* __restrict__ gkv,
    const float* __restrict__ fcos, const float* __restrict__ fsin,
    const int* __restrict__ pH, const int* __restrict__ pW)
{
    __half* T = blockIdx.y ? Tk : Tq;
    const float* g = blockIdx.y ? gkv : gqv;
    const int row = blockIdx.x;
    __half* p = T + (size_t)row * Dm;
    const int tid = threadIdx.x;

    // Load 3 pairs (pair index pj = tid + k*256 -> elements 2pj, 2pj+1)
    float2 vf[3];
    float ss = 0.f;
    #pragma unroll
    for (int k = 0; k < 3; k++) {
        int pj = tid + k * 256;
        vf[k] = __half22float2(*(const __half2*)(p + 2 * pj));
        ss += vf[k].x * vf[k].x + vf[k].y * vf[k].y;
    }

    __shared__ float red[8];
    const int lane = tid & 31, wid = tid >> 5;
    #pragma unroll
    for (int off = 16; off >= 1; off >>= 1)
        ss += __shfl_xor_sync(0xffffffffu, ss, off);
    if (lane == 0) red[wid] = ss;
    __syncthreads();
    if (wid == 0) {
        float v = (lane < 8) ? red[lane] : 0.f;
        #pragma unroll
        for (int off = 4; off >= 1; off >>= 1)
            v += __shfl_xor_sync(0xffffffffu, v, off);
        if (lane == 0) red[0] = rsqrtf(v * (1.f / Dm) + EPSF);
    }
    __syncthreads();
    const float rms = red[0];

    const int H = *pH, W = *pW;
    const int f = row / (H * W);
    const int hh = (row / W) % H;
    const int ww = row % W;

    #pragma unroll
    for (int k = 0; k < 3; k++) {
        int pj = tid + k * 256;
        int j = pj & 63;
        const int coord = (j < S1c) ? f : ((j < S1c + S2c) ? hh : ww);
        const float ccos = fcos[coord * Cc + j];
        const float csin = fsin[coord * Cc + j];
        float2 gg = *(const float2*)(g + 2 * pj);
        const float xr = vf[k].x * rms * gg.x;
        const float xi = vf[k].y * rms * gg.y;
        *(__half2*)(p + 2 * pj) = __floats2half2_rn(xr * ccos - xi * csin,
                                                    xr * csin + xi * ccos);
    }
}

// ---------------------------------------------------------------------------
// Flash attention, fp16 mma, ldmatrix loads. BQ=128, key tile 64.
// P in registers; 4-stage cp.async ring, one barrier/iter.
// ---------------------------------------------------------------------------
#define KSTR 136
#define VSTR 72
#define FNST 4
#define FL_SMEM ((FNST * 64 * KSTR + FNST * 128 * VSTR) * 2)

__global__ __launch_bounds__(256, 1) void flash_h(
    const __half* __restrict__ Q, const __half* __restrict__ K,
    const __half* __restrict__ Vt, __half* __restrict__ O)
{
    extern __shared__ __half smf[];
    __half* Ks = smf;
    __half* Vs = Ks + FNST * 64 * KSTR;
    const uint32_t sB = smem_u32(smf);

    const int t = threadIdx.x, lane = t & 31, wid = t >> 5;
    const int g = lane >> 2, t4 = lane & 3;
    const int head = blockIdx.y;
    const int q0 = blockIdx.x * 128;
    const __half* Qg = Q + (size_t)q0 * Dm + head * HDim;
    const __half* Kg0 = K + head * HDim;
    const __half* Vtg = Vt + (size_t)(head * HDim) * Lq;

    for (int i = t; i < 128 * 16; i += 256) {
        int r = i >> 4, c = i & 15;
        *(uint4*)(Ks + r * KSTR + c * 8) = *(const uint4*)(Qg + (size_t)r * Dm + c * 8);
    }
    __syncthreads();
    uint32_t qf[8][4];
    {
        const __half* bp = Ks + (wid * 16 + g) * KSTR;
        #pragma unroll
        for (int ks = 0; ks < 8; ks++) {
            qf[ks][0] = ldh2(bp + ks * 16 + 2 * t4);
            qf[ks][1] = ldh2(bp + 8 * KSTR + ks * 16 + 2 * t4);
            qf[ks][2] = ldh2(bp + ks * 16 + 2 * t4 + 8);
            qf[ks][3] = ldh2(bp + 8 * KSTR + ks * 16 + 2 * t4 + 8);
        }
    }
    __syncthreads();

    float o[16][4];
    #pragma unroll
    for (int j = 0; j < 16; j++) { o[j][0] = o[j][1] = o[j][2] = o[j][3] = 0.f; }
    float m0 = -1e30f, m1 = -1e30f, l0 = 0.f, l1 = 0.f;
    const float KS2 = 0.08838834764831845f * 1.4426950408889634f;

    auto issue = [&](int kt) {
        const int b = kt & (FNST - 1);
        const __half* Kg = Kg0 + (size_t)(kt * 64) * Dm;
        __half* Kd = Ks + b * 64 * KSTR;
        __half* Vd = Vs + b * 128 * VSTR;
        #pragma unroll
        for (int i = 0; i < 4; i++) {
            int idx = t + i * 256;
            int r = idx >> 4, c = idx & 15;
            cp16(Kd + r * KSTR + c * 8, Kg + (size_t)r * Dm + c * 8);
        }
        #pragma unroll
        for (int i = 0; i < 4; i++) {
            int idx = t + i * 256;
            int r = idx >> 3, c = idx & 7;
            cp16(Vd + r * VSTR + c * 8, Vtg + (size_t)r * Lq + kt * 64 + c * 8);
        }
        CP_COMMIT;
    };

    const uint32_t kOff =
        (uint32_t)((((lane & 7) + (lane >> 4) * 8) * KSTR + ((lane >> 3) & 1) * 8) * 2);
    const uint32_t vOff =
        (uint32_t)((((lane & 7) + (lane >> 4) * 8) * VSTR + ((lane >> 3) & 1) * 8) * 2);

    issue(0); issue(1);
    const int NT = Lq / 64;
    for (int kt = 0; kt < NT; kt++) {
        const int b = kt & (FNST - 1);
        if (kt + 2 < NT) { issue(kt + 2); CP_WAIT(2); }
        else if (kt + 1 < NT) { CP_WAIT(1); }
        else { CP_WAIT(0); }
        __syncthreads();

        const uint32_t stK = sB + (uint32_t)(b * 64 * KSTR * 2);
        const uint32_t stV = sB + (uint32_t)((FNST * 64 * KSTR + b * 128 * VSTR) * 2);

        float s[8][4];
        #pragma unroll
        for (int j = 0; j < 8; j++) { s[j][0] = s[j][1] = s[j][2] = s[j][3] = 0.f; }
        #pragma unroll
        for (int ks = 0; ks < 8; ks++) {
            uint32_t kf[8][2];
            #pragma unroll
            for (int jj = 0; jj < 4; jj++)
                ldsm4(kf[2 * jj][0], kf[2 * jj][1], kf[2 * jj + 1][0], kf[2 * jj + 1][1],
                      stK + kOff + jj * 16 * KSTR * 2 + ks * 32);
            #pragma unroll
            for (int j = 0; j < 8; j++)
                mma16(s[j], qf[ks], kf[j][0], kf[j][1]);
        }

        float mx0 = -1e30f, mx1 = -1e30f;
        #pragma unroll
        for (int j = 0; j < 8; j++) {
            mx0 = fmaxf(mx0, fmaxf(s[j][0], s[j][1]));
            mx1 = fmaxf(mx1, fmaxf(s[j][2], s[j][3]));
        }
        mx0 *= KS2; mx1 *= KS2;
        mx0 = fmaxf(mx0, __shfl_xor_sync(0xffffffffu, mx0, 1));
        mx0 = fmaxf(mx0, __shfl_xor_sync(0xffffffffu, mx0, 2));
        mx1 = fmaxf(mx1, __shfl_xor_sync(0xffffffffu, mx1, 1));
        mx1 = fmaxf(mx1, __shfl_xor_sync(0xffffffffu, mx1, 2));
        float nm0 = fmaxf(m0, mx0), nm1 = fmaxf(m1, mx1);
        float corr0 = ex2f(m0 - nm0), corr1 = ex2f(m1 - nm1);
        m0 = nm0; m1 = nm1;
        float r0 = 0.f, r1 = 0.f;
        uint32_t ph[8][2];
        #pragma unroll
        for (int j = 0; j < 8; j++) {
            float p00 = ex2f(s[j][0] * KS2 - m0);
            float p01 = ex2f(s[j][1] * KS2 - m0);
            float p10 = ex2f(s[j][2] * KS2 - m1);
            float p11 = ex2f(s[j][3] * KS2 - m1);
            r0 += p00 + p01; r1 += p10 + p11;
            ph[j][0] = packh2(p00, p01);
            ph[j][1] = packh2(p10, p11);
        }
        r0 += __shfl_xor_sync(0xffffffffu, r0, 1);
        r0 += __shfl_xor_sync(0xffffffffu, r0, 2);
        r1 += __shfl_xor_sync(0xffffffffu, r1, 1);
        r1 += __shfl_xor_sync(0xffffffffu, r1, 2);
        l0 = l0 * corr0 + r0;
        l1 = l1 * corr1 + r1;
        #pragma unroll
        for (int j = 0; j < 16; j++) {
            o[j][0] *= corr0; o[j][1] *= corr0;
            o[j][2] *= corr1; o[j][3] *= corr1;
        }

        #pragma unroll
        for (int mm = 0; mm < 4; mm++) {
            uint32_t a[4] = { ph[2 * mm][0], ph[2 * mm][1],
                              ph[2 * mm + 1][0], ph[2 * mm + 1][1] };
            #pragma unroll
            for (int jj = 0; jj < 8; jj++) {
                uint32_t v0, v1, v2, v3;
                ldsm4(v0, v1, v2, v3, stV + vOff + jj * 16 * VSTR * 2 + mm * 32);
                mma16(o[2 * jj], a, v0, v1);
                mma16(o[2 * jj + 1], a, v2, v3);
            }
        }
    }

    const float inv0 = 1.f / l0, inv1 = 1.f / l1;
    __half* O0 = O + (size_t)(q0 + wid * 16 + g) * Dm + head * HDim + 2 * t4;
    __half* O1 = O0 + 8 * (size_t)Dm;
    #pragma unroll
    for (int j = 0; j < 16; j++) {
        *(__half2*)(O0 + j * 8) = __floats2half2_rn(o[j][0] * inv0, o[j][1] * inv0);
        *(__half2*)(O1 + j * 8) = __floats2half2_rn(o[j][2] * inv1, o[j][3] * inv1);
    }
}

// ---------------------------------------------------------------------------
// Launch
// ---------------------------------------------------------------------------
extern "C" void kernel_launch(void* const* d_in, const int* in_sizes, int n_in,
                              void* d_out, int out_size)
{
    const float* x    = (const float*)d_in[0];
    const float* wq   = (const float*)d_in[1];
    const float* wk   = (const float*)d_in[2];
    const float* wv   = (const float*)d_in[3];
    const float* wo   = (const float*)d_in[4];
    const float* bq   = (const float*)d_in[5];
    const float* bk   = (const float*)d_in[6];
    const float* bv   = (const float*)d_in[7];
    const float* bo   = (const float*)d_in[8];
    const float* gq   = (const float*)d_in[9];
    const float* gk   = (const float*)d_in[10];
    const float* fcos = (const float*)d_in[11];
    const float* fsin = (const float*)d_in[12];
    // d_in[13] = seq_lens (all == L)
    const int* pH = (const int*)d_in[15];
    const int* pW = (const int*)d_in[16];
    float* out = (float*)d_out;

    __half *Xh, *Wc, *Woh, *Qh, *Kh, *Vt, *Ah;
    cudaGetSymbolAddress((void**)&Xh, g_Xh);
    cudaGetSymbolAddress((void**)&Wc, g_Wc);
    cudaGetSymbolAddress((void**)&Woh, g_Woh);
    cudaGetSymbolAddress((void**)&Qh, g_Qh);
    cudaGetSymbolAddress((void**)&Kh, g_Kh);
    cudaGetSymbolAddress((void**)&Vt, g_Vt);
    cudaGetSymbolAddress((void**)&Ah, g_Ah);

    cudaFuncSetAttribute(gemm_qkv, cudaFuncAttributeMaxDynamicSharedMemorySize, G_SMEM);
    cudaFuncSetAttribute(gemm_o, cudaFuncAttributeMaxDynamicSharedMemorySize, G_SMEM);
    cudaFuncSetAttribute(flash_h, cudaFuncAttributeMaxDynamicSharedMemorySize, FL_SMEM);

    const int nX = Lq * Dm, nW = Dm * Dm;
    to_half<<<nX / 8 / 256, 256>>>(x, Xh, nX);
    to_half4<<<dim3(nW / 8 / 256, 4), 256>>>(wq, wk, wv, wo,
                                             Wc, Wc + (size_t)Dm * Dm,
                                             Wc + 2 * (size_t)Dm * Dm, Woh, nW);

    gemm_qkv<<<dim3(3 * Dm / 128, Lq / 128), 256, G_SMEM>>>(
        Xh, Wc, bq, bk, bv, Qh, Kh, Vt);

    rmsnorm_rope_h<<<dim3(Lq, 2), 256>>>(Qh, Kh, gq, gk, fcos, fsin, pH, pW);

    flash_h<<<dim3(Lq / 128, NH), 256, FL_SMEM>>>(Qh, Kh, Vt, Ah);

    gemm_o<<<dim3(Dm / 128, Lq / 128), 256, G_SMEM>>>(Ah, Woh, bo, out);
}